// round 1
// baseline (speedup 1.0000x reference)
#include <cuda_runtime.h>
#include <math.h>

// Problem constants
#define GB 4
#define GT 1024
#define GF 1024
#define DIM 1024
#define GH 16
#define HD 64

// Scratch (allocation-free rule: __device__ globals)
__device__ float g_Q[GB*GT*DIM];
__device__ float g_K[GB*GF*DIM];
__device__ float g_V[GB*GF*DIM];
__device__ float g_A[GB*GT*DIM];

// ---------------------------------------------------------------------------
// GEMM: C[M,N] = A[M,K] @ B[N,K]^T + bias[N]   (both operands K-contiguous)
// 128x128 block, BK=16, 256 threads, 8x8 per thread.
// ---------------------------------------------------------------------------
#define BM 128
#define BN 128
#define BKK 16

__global__ __launch_bounds__(256) void gemm_nt_bias(
    const float* __restrict__ A, const float* __restrict__ B,
    const float* __restrict__ bias, float* __restrict__ C,
    int M, int N, int K)
{
    __shared__ float As[BKK][BM + 4];
    __shared__ float Bs[BKK][BN + 4];

    const int tid  = threadIdx.x;
    const int bm   = blockIdx.y * BM;
    const int bn   = blockIdx.x * BN;
    const int tx   = tid & 15;
    const int ty   = tid >> 4;
    const int row0 = ty * 8;
    const int col0 = tx * 8;

    float acc[8][8];
#pragma unroll
    for (int i = 0; i < 8; i++)
#pragma unroll
        for (int j = 0; j < 8; j++) acc[i][j] = 0.0f;

    for (int kt = 0; kt < K; kt += BKK) {
        // Load tiles (transpose into [k][m]/[k][n])
#pragma unroll
        for (int l = 0; l < 2; l++) {
            int idx = tid + l * 256;        // 0..511 float4 slots
            int r   = idx >> 2;             // 0..127
            int c   = (idx & 3) << 2;       // 0,4,8,12
            float4 va = *(const float4*)&A[(size_t)(bm + r) * K + kt + c];
            As[c + 0][r] = va.x; As[c + 1][r] = va.y;
            As[c + 2][r] = va.z; As[c + 3][r] = va.w;
            float4 vb = *(const float4*)&B[(size_t)(bn + r) * K + kt + c];
            Bs[c + 0][r] = vb.x; Bs[c + 1][r] = vb.y;
            Bs[c + 2][r] = vb.z; Bs[c + 3][r] = vb.w;
        }
        __syncthreads();

#pragma unroll
        for (int k = 0; k < BKK; k++) {
            float af[8], bf[8];
#pragma unroll
            for (int i = 0; i < 8; i++) af[i] = As[k][row0 + i];
#pragma unroll
            for (int j = 0; j < 8; j++) bf[j] = Bs[k][col0 + j];
#pragma unroll
            for (int i = 0; i < 8; i++)
#pragma unroll
                for (int j = 0; j < 8; j++)
                    acc[i][j] += af[i] * bf[j];
        }
        __syncthreads();
    }

    // Epilogue: add bias, vectorized store
#pragma unroll
    for (int i = 0; i < 8; i++) {
        float4 o0, o1;
        o0.x = acc[i][0] + bias[bn + col0 + 0];
        o0.y = acc[i][1] + bias[bn + col0 + 1];
        o0.z = acc[i][2] + bias[bn + col0 + 2];
        o0.w = acc[i][3] + bias[bn + col0 + 3];
        o1.x = acc[i][4] + bias[bn + col0 + 4];
        o1.y = acc[i][5] + bias[bn + col0 + 5];
        o1.z = acc[i][6] + bias[bn + col0 + 6];
        o1.w = acc[i][7] + bias[bn + col0 + 7];
        size_t base = (size_t)(bm + row0 + i) * N + bn + col0;
        *(float4*)&C[base]     = o0;
        *(float4*)&C[base + 4] = o1;
    }
}

// ---------------------------------------------------------------------------
// Flash-attention (fp32, online softmax).
// Block: 128 query rows x full head; loops over KV in 64-row tiles.
// grid = (T/128, H, B), 256 threads.
// Q,K,V layout: [(b*1024 + t), h*64 + d] row-major (stride 1024).
// ---------------------------------------------------------------------------
#define TT 128
#define FT 64
#define PADW 65

__global__ __launch_bounds__(256) void attn_kernel(
    const float* __restrict__ Q, const float* __restrict__ Km,
    const float* __restrict__ Vm, const int* __restrict__ mask,
    float* __restrict__ O)
{
    extern __shared__ float sm[];
    float* Qs   = sm;                      // [TT][PADW]
    float* Ks   = Qs + TT * PADW;          // [FT][PADW]
    float* Vs   = Ks + FT * PADW;          // [FT][PADW]
    float* Ps   = Vs + FT * PADW;          // [TT][PADW]
    float* mrow = Ps + TT * PADW;          // [TT]
    float* lrow = mrow + TT;               // [TT]
    float* crow = lrow + TT;               // [TT]

    const int tid = threadIdx.x;
    const int tt  = blockIdx.x;
    const int h   = blockIdx.y;
    const int b   = blockIdx.z;
    const int t0  = tt * TT;

    const int tx = tid & 15;               // 0..15
    const int ty = tid >> 4;               // 0..15
    const int i0 = ty * 8;                 // query row group (8 rows)
    const int j0 = tx * 4;                 // kv col group (4 cols)

    // Load Q tile: 128 rows x 64 cols = 2048 float4
#pragma unroll
    for (int l = 0; l < 8; l++) {
        int idx = tid + l * 256;
        int r = idx >> 4;
        int c = (idx & 15) << 2;
        float4 v = *(const float4*)&Q[((size_t)(b * GT + t0 + r)) * DIM + h * HD + c];
        float* q = &Qs[r * PADW + c];
        q[0] = v.x; q[1] = v.y; q[2] = v.z; q[3] = v.w;
    }
    if (tid < TT) { mrow[tid] = -1e30f; lrow[tid] = 0.0f; }

    float acc[8][4];
#pragma unroll
    for (int i = 0; i < 8; i++)
#pragma unroll
        for (int d = 0; d < 4; d++) acc[i][d] = 0.0f;

    for (int ft = 0; ft < GF / FT; ft++) {
        const int f0 = ft * FT;
        __syncthreads();   // fences Q load (first iter) + prev-iter tile reads

        // Load K/V tiles: 64x64 each
#pragma unroll
        for (int l = 0; l < 4; l++) {
            int idx = tid + l * 256;
            int r = idx >> 4;
            int c = (idx & 15) << 2;
            size_t g = ((size_t)(b * GF + f0 + r)) * DIM + h * HD + c;
            float4 kv = *(const float4*)&Km[g];
            float* kp = &Ks[r * PADW + c];
            kp[0] = kv.x; kp[1] = kv.y; kp[2] = kv.z; kp[3] = kv.w;
            float4 vv = *(const float4*)&Vm[g];
            float* vp = &Vs[r * PADW + c];
            vp[0] = vv.x; vp[1] = vv.y; vp[2] = vv.z; vp[3] = vv.w;
        }
        __syncthreads();

        // S = Q K^T (each thread 8x4)
        float s[8][4];
#pragma unroll
        for (int i = 0; i < 8; i++)
#pragma unroll
            for (int j = 0; j < 4; j++) s[i][j] = 0.0f;

        for (int d = 0; d < HD; d++) {
            float af[8], bf[4];
#pragma unroll
            for (int i = 0; i < 8; i++) af[i] = Qs[(i0 + i) * PADW + d];
#pragma unroll
            for (int j = 0; j < 4; j++) bf[j] = Ks[(j0 + j) * PADW + d];
#pragma unroll
            for (int i = 0; i < 8; i++)
#pragma unroll
                for (int j = 0; j < 4; j++) s[i][j] += af[i] * bf[j];
        }

        // scale + mask, stash raw into Ps for row-max
#pragma unroll
        for (int i = 0; i < 8; i++) {
            const int* mrp = &mask[((size_t)(b * GT + t0 + i0 + i)) * GF + f0 + j0];
#pragma unroll
            for (int j = 0; j < 4; j++) {
                float val = (mrp[j] != 0) ? s[i][j] * 0.125f : -10000.0f;
                s[i][j] = val;
                Ps[(i0 + i) * PADW + j0 + j] = val;
            }
        }
        __syncthreads();

        // Row max + correction factor (one thread per row)
        if (tid < TT) {
            float mt = -1e30f;
            const float* pr = &Ps[tid * PADW];
#pragma unroll 8
            for (int j = 0; j < FT; j++) mt = fmaxf(mt, pr[j]);
            float mo = mrow[tid];
            float mn = fmaxf(mo, mt);
            crow[tid] = __expf(mo - mn);
            mrow[tid] = mn;
        }
        __syncthreads();

        // exp (distributed across all 256 threads), write P
#pragma unroll
        for (int i = 0; i < 8; i++) {
            float m = mrow[i0 + i];
#pragma unroll
            for (int j = 0; j < 4; j++) {
                float p = __expf(s[i][j] - m);
                Ps[(i0 + i) * PADW + j0 + j] = p;
            }
        }
        __syncthreads();

        // Row sum -> l update (concurrent with O accumulation; no RAW hazard)
        if (tid < TT) {
            float ls = 0.0f;
            const float* pr = &Ps[tid * PADW];
#pragma unroll 8
            for (int j = 0; j < FT; j++) ls += pr[j];
            lrow[tid] = lrow[tid] * crow[tid] + ls;
        }

        // Rescale accumulators, then O += P V  (output cols d0 = j0)
        float cf[8];
#pragma unroll
        for (int i = 0; i < 8; i++) cf[i] = crow[i0 + i];
#pragma unroll
        for (int i = 0; i < 8; i++)
#pragma unroll
            for (int d = 0; d < 4; d++) acc[i][d] *= cf[i];

        for (int j = 0; j < FT; j++) {
            float pf[8], vf[4];
#pragma unroll
            for (int i = 0; i < 8; i++) pf[i] = Ps[(i0 + i) * PADW + j];
#pragma unroll
            for (int d = 0; d < 4; d++) vf[d] = Vs[j * PADW + j0 + d];
#pragma unroll
            for (int i = 0; i < 8; i++)
#pragma unroll
                for (int d = 0; d < 4; d++) acc[i][d] += pf[i] * vf[d];
        }
    }

    __syncthreads();   // lrow final
#pragma unroll
    for (int i = 0; i < 8; i++) {
        float inv = 1.0f / lrow[i0 + i];
        float4 o;
        o.x = acc[i][0] * inv;
        o.y = acc[i][1] * inv;
        o.z = acc[i][2] * inv;
        o.w = acc[i][3] * inv;
        *(float4*)&O[((size_t)(b * GT + t0 + i0 + i)) * DIM + h * HD + j0] = o;
    }
}

// ---------------------------------------------------------------------------
// Launch
// ---------------------------------------------------------------------------
#define ATT_SMEM ((TT*PADW + FT*PADW + FT*PADW + TT*PADW + 3*TT) * (int)sizeof(float))

extern "C" void kernel_launch(void* const* d_in, const int* in_sizes, int n_in,
                              void* d_out, int out_size)
{
    const float* X_to   = (const float*)d_in[0];
    const float* X_from = (const float*)d_in[1];
    const int*   maskp  = (const int*)  d_in[2];
    const float* Wq = (const float*)d_in[3];
    const float* bq = (const float*)d_in[4];
    const float* Wk = (const float*)d_in[5];
    const float* bk = (const float*)d_in[6];
    const float* Wv = (const float*)d_in[7];
    const float* bv = (const float*)d_in[8];
    const float* Wo = (const float*)d_in[9];
    const float* bo = (const float*)d_in[10];
    float* out = (float*)d_out;

    float *pQ, *pK, *pV, *pA;
    cudaGetSymbolAddress((void**)&pQ, g_Q);
    cudaGetSymbolAddress((void**)&pK, g_K);
    cudaGetSymbolAddress((void**)&pV, g_V);
    cudaGetSymbolAddress((void**)&pA, g_A);

    cudaFuncSetAttribute(attn_kernel,
                         cudaFuncAttributeMaxDynamicSharedMemorySize, ATT_SMEM);

    const int M = GB * GT;     // 4096
    const int N = DIM;         // 1024
    const int K = DIM;         // 1024
    dim3 gg(N / BN, M / BM);   // (8, 32)
    dim3 gb(256);

    // Projections. NOTE the reference's deliberate swap: K uses Wv/bv, V uses Wk/bk.
    gemm_nt_bias<<<gg, gb>>>(X_to,   Wq, bq, pQ, M, N, K);
    gemm_nt_bias<<<gg, gb>>>(X_from, Wv, bv, pK, M, N, K);
    gemm_nt_bias<<<gg, gb>>>(X_from, Wk, bk, pV, M, N, K);

    dim3 ag(GT / TT, GH, GB);  // (8, 16, 4)
    attn_kernel<<<ag, 256, ATT_SMEM>>>(pQ, pK, pV, maskp, pA);

    // Output projection straight into d_out (covers every element).
    gemm_nt_bias<<<gg, gb>>>(pA, Wo, bo, out, M, N, K);
}

// round 3
// speedup vs baseline: 1.4724x; 1.4724x over previous
#include <cuda_runtime.h>
#include <cuda_bf16.h>
#include <cstdint>
#include <math.h>

// Problem constants
#define GB 4
#define GT 1024
#define GF 1024
#define DIM 1024
#define GH 16
#define HD 64
#define MTOT (GB*GT)   // 4096

// ---------------------------------------------------------------------------
// Scratch (__device__ globals; allocation-free rule)
// ---------------------------------------------------------------------------
__device__ float g_Q[MTOT*DIM];
__device__ float g_K[MTOT*DIM];
__device__ float g_V[MTOT*DIM];
__device__ float g_A[MTOT*DIM];

__device__ __nv_bfloat16 g_XtH[MTOT*DIM], g_XtL[MTOT*DIM];
__device__ __nv_bfloat16 g_XfH[MTOT*DIM], g_XfL[MTOT*DIM];
__device__ __nv_bfloat16 g_AH [MTOT*DIM], g_AL [MTOT*DIM];
__device__ __nv_bfloat16 g_WqH[DIM*DIM],  g_WqL[DIM*DIM];
__device__ __nv_bfloat16 g_WkH[DIM*DIM],  g_WkL[DIM*DIM];
__device__ __nv_bfloat16 g_WvH[DIM*DIM],  g_WvL[DIM*DIM];
__device__ __nv_bfloat16 g_WoH[DIM*DIM],  g_WoL[DIM*DIM];

// ---------------------------------------------------------------------------
// Helpers
// ---------------------------------------------------------------------------
__device__ __forceinline__ uint32_t smem_u32(const void* p){
    uint32_t a;
    asm("{ .reg .u64 t; cvta.to.shared.u64 t, %1; cvt.u32.u64 %0, t; }"
        : "=r"(a) : "l"(p));
    return a;
}

__device__ __forceinline__ void ldsm4(uint32_t* r, uint32_t addr){
    asm volatile("ldmatrix.sync.aligned.m8n8.x4.shared.b16 {%0,%1,%2,%3}, [%4];"
        : "=r"(r[0]), "=r"(r[1]), "=r"(r[2]), "=r"(r[3]) : "r"(addr));
}
__device__ __forceinline__ void ldsm2(uint32_t* r, uint32_t addr){
    asm volatile("ldmatrix.sync.aligned.m8n8.x2.shared.b16 {%0,%1}, [%2];"
        : "=r"(r[0]), "=r"(r[1]) : "r"(addr));
}
__device__ __forceinline__ void mma16816(float* d, const uint32_t* a, const uint32_t* b){
    asm volatile("mma.sync.aligned.m16n8k16.row.col.f32.bf16.bf16.f32 "
        "{%0,%1,%2,%3}, {%4,%5,%6,%7}, {%8,%9}, {%0,%1,%2,%3};"
        : "+f"(d[0]), "+f"(d[1]), "+f"(d[2]), "+f"(d[3])
        : "r"(a[0]), "r"(a[1]), "r"(a[2]), "r"(a[3]), "r"(b[0]), "r"(b[1]));
}

// Branch-free exp on FMA/ALU pipes only (no MUFU, no F2I).
// Valid for x <= ~80; large-negative x clamps to ~exp(-87) ~= 1.6e-38.
__device__ __forceinline__ float fast_exp(float x){
    float xc = fmaxf(x, -87.0f);
    float r  = fmaf(xc, 1.4426950408889634f, 12582912.0f); // round(x*log2e) in mantissa
    int   n  = __float_as_int(r) - 0x4B400000;
    float fi = r - 12582912.0f;
    float g  = fmaf(fi, -0.6931471805599453f, xc);         // |g| <= 0.3466
    float p  = 8.3333337e-3f;                               // 1/120
    p = fmaf(p, g, 4.1666668e-2f);                          // 1/24
    p = fmaf(p, g, 1.6666667e-1f);                          // 1/6
    p = fmaf(p, g, 0.5f);
    p = fmaf(p, g, 1.0f);
    p = fmaf(p, g, 1.0f);
    return p * __int_as_float((n << 23) + 0x3F800000);
}

// ---------------------------------------------------------------------------
// fp32 -> (bf16 hi, bf16 lo) split
// ---------------------------------------------------------------------------
__global__ __launch_bounds__(256) void split_bf16(
    const float4* __restrict__ x, uint2* __restrict__ h, uint2* __restrict__ l, int n4)
{
    int i = blockIdx.x * 256 + threadIdx.x;
    if (i >= n4) return;
    float4 v = x[i];
    union { __nv_bfloat16 b[4]; uint2 u; } H, L;
    H.b[0] = __float2bfloat16(v.x);
    H.b[1] = __float2bfloat16(v.y);
    H.b[2] = __float2bfloat16(v.z);
    H.b[3] = __float2bfloat16(v.w);
    L.b[0] = __float2bfloat16(v.x - __bfloat162float(H.b[0]));
    L.b[1] = __float2bfloat16(v.y - __bfloat162float(H.b[1]));
    L.b[2] = __float2bfloat16(v.z - __bfloat162float(H.b[2]));
    L.b[3] = __float2bfloat16(v.w - __bfloat162float(H.b[3]));
    h[i] = H.u;
    l[i] = L.u;
}

// ---------------------------------------------------------------------------
// mma.sync bf16x3 GEMM: C[M,N] = (Ah+Al)[M,K] @ (Bh+Bl)[N,K]^T + bias
// D += Ah*Bh + Ah*Bl + Al*Bh in fp32 accumulators.
// 128x128x32 block tile, 256 threads (8 warps), 64x32 warp tile.
// ---------------------------------------------------------------------------
#define BM 128
#define BN 128
#define BK 32
#define LDT 40                       // padded smem row (bf16 units)
#define TSZ (128*LDT)                // one tile, bf16 units
#define GEMM_SMEM (4*TSZ*2)          // 40960 bytes

__global__ __launch_bounds__(256) void gemm_mma_bf16x3(
    const __nv_bfloat16* __restrict__ Ah, const __nv_bfloat16* __restrict__ Al,
    const __nv_bfloat16* __restrict__ Bh, const __nv_bfloat16* __restrict__ Bl,
    const float* __restrict__ bias, float* __restrict__ C)
{
    extern __shared__ __nv_bfloat16 smb[];
    __nv_bfloat16* tiles[4] = { smb, smb + TSZ, smb + 2*TSZ, smb + 3*TSZ };

    const int tid = threadIdx.x, wid = tid >> 5, lane = tid & 31;
    const int bm = blockIdx.y * BM, bn = blockIdx.x * BN;
    const int wm = (wid & 1) * 64;     // warp row offset in tile
    const int wn = (wid >> 1) * 32;    // warp col offset in tile

    const __nv_bfloat16* src[4];
    src[0] = Ah + (size_t)bm * DIM;
    src[1] = Al + (size_t)bm * DIM;
    src[2] = Bh + (size_t)bn * DIM;
    src[3] = Bl + (size_t)bn * DIM;

    float acc[4][4][4];
#pragma unroll
    for (int i = 0; i < 4; i++)
#pragma unroll
        for (int j = 0; j < 4; j++)
#pragma unroll
            for (int k = 0; k < 4; k++) acc[i][j][k] = 0.0f;

    // ldmatrix lane-address components
    const int seg = lane >> 3, lr = lane & 7;
    const int a_row = wm + (seg & 1) * 8 + lr;       // + mt*16
    const int a_kof = (seg >> 1) * 8;                // + ks*16
    const int b_row = wn + lr;                       // + nt*8
    const int b_kof = (seg & 1) * 8;                 // + ks*16

    const uint32_t sb = smem_u32(smb);
    const uint32_t aAh0 = sb + (a_row * LDT + a_kof) * 2;
    const uint32_t aAl0 = aAh0 + TSZ * 2;
    const uint32_t aBh0 = sb + ((b_row * LDT + b_kof) + 2 * TSZ) * 2;
    const uint32_t aBl0 = aBh0 + TSZ * 2;

    for (int kc = 0; kc < DIM / BK; kc++) {
        __syncthreads();
        // Load 4 tiles: 128 rows x 32 bf16 = 512 uint4 each, 2 per thread
#pragma unroll
        for (int t = 0; t < 4; t++) {
            const __nv_bfloat16* s = src[t] + kc * BK;
            __nv_bfloat16* d = tiles[t];
#pragma unroll
            for (int j = 0; j < 2; j++) {
                int idx = tid + j * 256;         // 0..511
                int r = idx >> 2;
                int c = (idx & 3) * 8;
                *(uint4*)&d[r * LDT + c] = *(const uint4*)&s[(size_t)r * DIM + c];
            }
        }
        __syncthreads();

#pragma unroll
        for (int ks = 0; ks < 2; ks++) {
            const uint32_t ko = ks * 32;   // 16 bf16 = 32 bytes
            uint32_t bh[4][2], bl[4][2];
#pragma unroll
            for (int nt = 0; nt < 4; nt++) {
                ldsm2(bh[nt], aBh0 + nt * (8 * LDT * 2) + ko);
                ldsm2(bl[nt], aBl0 + nt * (8 * LDT * 2) + ko);
            }
#pragma unroll
            for (int mt = 0; mt < 4; mt++) {
                uint32_t ah[4], al[4];
                ldsm4(ah, aAh0 + mt * (16 * LDT * 2) + ko);
                ldsm4(al, aAl0 + mt * (16 * LDT * 2) + ko);
#pragma unroll
                for (int nt = 0; nt < 4; nt++) {
                    mma16816(acc[mt][nt], ah, bh[nt]);
                    mma16816(acc[mt][nt], ah, bl[nt]);
                    mma16816(acc[mt][nt], al, bh[nt]);
                }
            }
        }
    }

    // Epilogue: direct global stores with bias
    const int gr = lane >> 2;          // 0..7
    const int gc = (lane & 3) * 2;     // 0,2,4,6
#pragma unroll
    for (int mt = 0; mt < 4; mt++) {
#pragma unroll
        for (int nt = 0; nt < 4; nt++) {
            int col  = bn + wn + nt * 8 + gc;
            float b0 = bias[col], b1 = bias[col + 1];
            size_t r0 = (size_t)(bm + wm + mt * 16 + gr) * DIM + col;
            size_t r1 = r0 + 8 * DIM;
            float2 v0 = { acc[mt][nt][0] + b0, acc[mt][nt][1] + b1 };
            float2 v1 = { acc[mt][nt][2] + b0, acc[mt][nt][3] + b1 };
            *(float2*)&C[r0] = v0;
            *(float2*)&C[r1] = v1;
        }
    }
}

// ---------------------------------------------------------------------------
// Flash-attention (fp32, online softmax) — R1 structure, fast_exp instead of MUFU
// ---------------------------------------------------------------------------
#define TT 128
#define FT 64
#define PADW 65

__global__ __launch_bounds__(256) void attn_kernel(
    const float* __restrict__ Q, const float* __restrict__ Km,
    const float* __restrict__ Vm, const int* __restrict__ mask,
    float* __restrict__ O)
{
    extern __shared__ float sm[];
    float* Qs   = sm;
    float* Ks   = Qs + TT * PADW;
    float* Vs   = Ks + FT * PADW;
    float* Ps   = Vs + FT * PADW;
    float* mrow = Ps + TT * PADW;
    float* lrow = mrow + TT;
    float* crow = lrow + TT;

    const int tid = threadIdx.x;
    const int tt  = blockIdx.x;
    const int h   = blockIdx.y;
    const int b   = blockIdx.z;
    const int t0  = tt * TT;

    const int tx = tid & 15;
    const int ty = tid >> 4;
    const int i0 = ty * 8;
    const int j0 = tx * 4;

#pragma unroll
    for (int l = 0; l < 8; l++) {
        int idx = tid + l * 256;
        int r = idx >> 4;
        int c = (idx & 15) << 2;
        float4 v = *(const float4*)&Q[((size_t)(b * GT + t0 + r)) * DIM + h * HD + c];
        float* q = &Qs[r * PADW + c];
        q[0] = v.x; q[1] = v.y; q[2] = v.z; q[3] = v.w;
    }
    if (tid < TT) { mrow[tid] = -1e30f; lrow[tid] = 0.0f; }

    float acc[8][4];
#pragma unroll
    for (int i = 0; i < 8; i++)
#pragma unroll
        for (int d = 0; d < 4; d++) acc[i][d] = 0.0f;

    for (int ft = 0; ft < GF / FT; ft++) {
        const int f0 = ft * FT;
        __syncthreads();

#pragma unroll
        for (int l = 0; l < 4; l++) {
            int idx = tid + l * 256;
            int r = idx >> 4;
            int c = (idx & 15) << 2;
            size_t g = ((size_t)(b * GF + f0 + r)) * DIM + h * HD + c;
            float4 kv = *(const float4*)&Km[g];
            float* kp = &Ks[r * PADW + c];
            kp[0] = kv.x; kp[1] = kv.y; kp[2] = kv.z; kp[3] = kv.w;
            float4 vv = *(const float4*)&Vm[g];
            float* vp = &Vs[r * PADW + c];
            vp[0] = vv.x; vp[1] = vv.y; vp[2] = vv.z; vp[3] = vv.w;
        }
        __syncthreads();

        float s[8][4];
#pragma unroll
        for (int i = 0; i < 8; i++)
#pragma unroll
            for (int j = 0; j < 4; j++) s[i][j] = 0.0f;

        for (int d = 0; d < HD; d++) {
            float af[8], bf[4];
#pragma unroll
            for (int i = 0; i < 8; i++) af[i] = Qs[(i0 + i) * PADW + d];
#pragma unroll
            for (int j = 0; j < 4; j++) bf[j] = Ks[(j0 + j) * PADW + d];
#pragma unroll
            for (int i = 0; i < 8; i++)
#pragma unroll
                for (int j = 0; j < 4; j++) s[i][j] += af[i] * bf[j];
        }

#pragma unroll
        for (int i = 0; i < 8; i++) {
            const int* mrp = &mask[((size_t)(b * GT + t0 + i0 + i)) * GF + f0 + j0];
#pragma unroll
            for (int j = 0; j < 4; j++) {
                float val = (mrp[j] != 0) ? s[i][j] * 0.125f : -10000.0f;
                s[i][j] = val;
                Ps[(i0 + i) * PADW + j0 + j] = val;
            }
        }
        __syncthreads();

        if (tid < TT) {
            float mt = -1e30f;
            const float* pr = &Ps[tid * PADW];
#pragma unroll 8
            for (int j = 0; j < FT; j++) mt = fmaxf(mt, pr[j]);
            float mo = mrow[tid];
            float mn = fmaxf(mo, mt);
            crow[tid] = fast_exp(mo - mn);
            mrow[tid] = mn;
        }
        __syncthreads();

#pragma unroll
        for (int i = 0; i < 8; i++) {
            float m = mrow[i0 + i];
#pragma unroll
            for (int j = 0; j < 4; j++) {
                float p = fast_exp(s[i][j] - m);
                Ps[(i0 + i) * PADW + j0 + j] = p;
            }
        }
        __syncthreads();

        if (tid < TT) {
            float ls = 0.0f;
            const float* pr = &Ps[tid * PADW];
#pragma unroll 8
            for (int j = 0; j < FT; j++) ls += pr[j];
            lrow[tid] = lrow[tid] * crow[tid] + ls;
        }

        float cf[8];
#pragma unroll
        for (int i = 0; i < 8; i++) cf[i] = crow[i0 + i];
#pragma unroll
        for (int i = 0; i < 8; i++)
#pragma unroll
            for (int d = 0; d < 4; d++) acc[i][d] *= cf[i];

        for (int j = 0; j < FT; j++) {
            float pf[8], vf[4];
#pragma unroll
            for (int i = 0; i < 8; i++) pf[i] = Ps[(i0 + i) * PADW + j];
#pragma unroll
            for (int d = 0; d < 4; d++) vf[d] = Vs[j * PADW + j0 + d];
#pragma unroll
            for (int i = 0; i < 8; i++)
#pragma unroll
                for (int d = 0; d < 4; d++) acc[i][d] += pf[i] * vf[d];
        }
    }

    __syncthreads();
#pragma unroll
    for (int i = 0; i < 8; i++) {
        float inv = 1.0f / lrow[i0 + i];
        float4 o;
        o.x = acc[i][0] * inv;
        o.y = acc[i][1] * inv;
        o.z = acc[i][2] * inv;
        o.w = acc[i][3] * inv;
        *(float4*)&O[((size_t)(b * GT + t0 + i0 + i)) * DIM + h * HD + j0] = o;
    }
}

#define ATT_SMEM ((TT*PADW + FT*PADW + FT*PADW + TT*PADW + 3*TT) * (int)sizeof(float))

// ---------------------------------------------------------------------------
// Launch
// ---------------------------------------------------------------------------
extern "C" void kernel_launch(void* const* d_in, const int* in_sizes, int n_in,
                              void* d_out, int out_size)
{
    const float* X_to   = (const float*)d_in[0];
    const float* X_from = (const float*)d_in[1];
    const int*   maskp  = (const int*)  d_in[2];
    const float* Wq = (const float*)d_in[3];
    const float* bq = (const float*)d_in[4];
    const float* Wk = (const float*)d_in[5];
    const float* bk = (const float*)d_in[6];
    const float* Wv = (const float*)d_in[7];
    const float* bv = (const float*)d_in[8];
    const float* Wo = (const float*)d_in[9];
    const float* bo = (const float*)d_in[10];
    float* out = (float*)d_out;

    float *pQ, *pK, *pV, *pA;
    cudaGetSymbolAddress((void**)&pQ, g_Q);
    cudaGetSymbolAddress((void**)&pK, g_K);
    cudaGetSymbolAddress((void**)&pV, g_V);
    cudaGetSymbolAddress((void**)&pA, g_A);

    __nv_bfloat16 *XtH, *XtL, *XfH, *XfL, *AH, *AL;
    __nv_bfloat16 *WqH, *WqL, *WkH, *WkL, *WvH, *WvL, *WoH, *WoL;
    cudaGetSymbolAddress((void**)&XtH, g_XtH); cudaGetSymbolAddress((void**)&XtL, g_XtL);
    cudaGetSymbolAddress((void**)&XfH, g_XfH); cudaGetSymbolAddress((void**)&XfL, g_XfL);
    cudaGetSymbolAddress((void**)&AH,  g_AH);  cudaGetSymbolAddress((void**)&AL,  g_AL);
    cudaGetSymbolAddress((void**)&WqH, g_WqH); cudaGetSymbolAddress((void**)&WqL, g_WqL);
    cudaGetSymbolAddress((void**)&WkH, g_WkH); cudaGetSymbolAddress((void**)&WkL, g_WkL);
    cudaGetSymbolAddress((void**)&WvH, g_WvH); cudaGetSymbolAddress((void**)&WvL, g_WvL);
    cudaGetSymbolAddress((void**)&WoH, g_WoH); cudaGetSymbolAddress((void**)&WoL, g_WoL);

    cudaFuncSetAttribute(attn_kernel,
                         cudaFuncAttributeMaxDynamicSharedMemorySize, ATT_SMEM);
    cudaFuncSetAttribute(gemm_mma_bf16x3,
                         cudaFuncAttributeMaxDynamicSharedMemorySize, GEMM_SMEM);

    const int nX4 = MTOT * DIM / 4;
    const int nW4 = DIM * DIM / 4;

    split_bf16<<<nX4 / 256, 256>>>((const float4*)X_to,   (uint2*)XtH, (uint2*)XtL, nX4);
    split_bf16<<<nX4 / 256, 256>>>((const float4*)X_from, (uint2*)XfH, (uint2*)XfL, nX4);
    split_bf16<<<nW4 / 256, 256>>>((const float4*)Wq, (uint2*)WqH, (uint2*)WqL, nW4);
    split_bf16<<<nW4 / 256, 256>>>((const float4*)Wk, (uint2*)WkH, (uint2*)WkL, nW4);
    split_bf16<<<nW4 / 256, 256>>>((const float4*)Wv, (uint2*)WvH, (uint2*)WvL, nW4);
    split_bf16<<<nW4 / 256, 256>>>((const float4*)Wo, (uint2*)WoH, (uint2*)WoL, nW4);

    dim3 gg(DIM / BN, MTOT / BM);   // (8, 32)

    // Projections. NOTE the reference's deliberate swap: K uses Wv/bv, V uses Wk/bk.
    gemm_mma_bf16x3<<<gg, 256, GEMM_SMEM>>>(XtH, XtL, WqH, WqL, bq, pQ);
    gemm_mma_bf16x3<<<gg, 256, GEMM_SMEM>>>(XfH, XfL, WvH, WvL, bv, pK);
    gemm_mma_bf16x3<<<gg, 256, GEMM_SMEM>>>(XfH, XfL, WkH, WkL, bk, pV);

    dim3 ag(GT / TT, GH, GB);       // (8, 16, 4)
    attn_kernel<<<ag, 256, ATT_SMEM>>>(pQ, pK, pV, maskp, pA);

    split_bf16<<<nX4 / 256, 256>>>((const float4*)pA, (uint2*)AH, (uint2*)AL, nX4);
    gemm_mma_bf16x3<<<gg, 256, GEMM_SMEM>>>(AH, AL, WoH, WoL, bo, out);
}

// round 4
// speedup vs baseline: 2.4160x; 1.6409x over previous
#include <cuda_runtime.h>
#include <cuda_bf16.h>
#include <cstdint>
#include <math.h>

// Problem constants
#define GB 4
#define GT 1024
#define GF 1024
#define DIM 1024
#define GH 16
#define HD 64
#define MTOT (GB*GT)   // 4096

// ---------------------------------------------------------------------------
// Scratch (__device__ globals; allocation-free rule)
// ---------------------------------------------------------------------------
__device__ __nv_bfloat16 g_QH[MTOT*DIM], g_QL[MTOT*DIM];
__device__ __nv_bfloat16 g_KH[MTOT*DIM], g_KL[MTOT*DIM];
__device__ __nv_bfloat16 g_VH[MTOT*DIM], g_VL[MTOT*DIM];
__device__ __nv_bfloat16 g_AH[MTOT*DIM], g_AL[MTOT*DIM];
__device__ __nv_bfloat16 g_XtH[MTOT*DIM], g_XtL[MTOT*DIM];
__device__ __nv_bfloat16 g_XfH[MTOT*DIM], g_XfL[MTOT*DIM];
__device__ __nv_bfloat16 g_WqH[DIM*DIM],  g_WqL[DIM*DIM];
__device__ __nv_bfloat16 g_WkH[DIM*DIM],  g_WkL[DIM*DIM];
__device__ __nv_bfloat16 g_WvH[DIM*DIM],  g_WvL[DIM*DIM];
__device__ __nv_bfloat16 g_WoH[DIM*DIM],  g_WoL[DIM*DIM];

// ---------------------------------------------------------------------------
// Helpers
// ---------------------------------------------------------------------------
__device__ __forceinline__ uint32_t smem_u32(const void* p){
    uint32_t a;
    asm("{ .reg .u64 t; cvta.to.shared.u64 t, %1; cvt.u32.u64 %0, t; }"
        : "=r"(a) : "l"(p));
    return a;
}
__device__ __forceinline__ void ldsm4(uint32_t* r, uint32_t addr){
    asm volatile("ldmatrix.sync.aligned.m8n8.x4.shared.b16 {%0,%1,%2,%3}, [%4];"
        : "=r"(r[0]), "=r"(r[1]), "=r"(r[2]), "=r"(r[3]) : "r"(addr));
}
__device__ __forceinline__ void ldsm4t(uint32_t* r, uint32_t addr){
    asm volatile("ldmatrix.sync.aligned.m8n8.x4.trans.shared.b16 {%0,%1,%2,%3}, [%4];"
        : "=r"(r[0]), "=r"(r[1]), "=r"(r[2]), "=r"(r[3]) : "r"(addr));
}
__device__ __forceinline__ void mma16816(float* d, const uint32_t* a, const uint32_t* b){
    asm volatile("mma.sync.aligned.m16n8k16.row.col.f32.bf16.bf16.f32 "
        "{%0,%1,%2,%3}, {%4,%5,%6,%7}, {%8,%9}, {%0,%1,%2,%3};"
        : "+f"(d[0]), "+f"(d[1]), "+f"(d[2]), "+f"(d[3])
        : "r"(a[0]), "r"(a[1]), "r"(a[2]), "r"(a[3]), "r"(b[0]), "r"(b[1]));
}
// pack two fp32 -> bf16x2 reg: low half <- lo, high half <- hi
__device__ __forceinline__ uint32_t packbf(float hi, float lo){
    uint32_t r;
    asm("cvt.rn.bf16x2.f32 %0, %1, %2;" : "=r"(r) : "f"(hi), "f"(lo));
    return r;
}
__device__ __forceinline__ float bflo(uint32_t r){ return __int_as_float(r << 16); }
__device__ __forceinline__ float bfhi(uint32_t r){ return __int_as_float(r & 0xFFFF0000u); }

// Branch-free exp on FMA/ALU pipes only.
__device__ __forceinline__ float fast_exp(float x){
    float xc = fmaxf(x, -87.0f);
    float r  = fmaf(xc, 1.4426950408889634f, 12582912.0f);
    int   n  = __float_as_int(r) - 0x4B400000;
    float fi = r - 12582912.0f;
    float g  = fmaf(fi, -0.6931471805599453f, xc);
    float p  = 8.3333337e-3f;
    p = fmaf(p, g, 4.1666668e-2f);
    p = fmaf(p, g, 1.6666667e-1f);
    p = fmaf(p, g, 0.5f);
    p = fmaf(p, g, 1.0f);
    p = fmaf(p, g, 1.0f);
    return p * __int_as_float((n << 23) + 0x3F800000);
}

#define CP_ASYNC16(sm, gp) \
    asm volatile("cp.async.cg.shared.global [%0], [%1], 16;" :: "r"(sm), "l"(gp))
#define CP_COMMIT() asm volatile("cp.async.commit_group;")
#define CP_WAIT1()  asm volatile("cp.async.wait_group 1;")

// ---------------------------------------------------------------------------
// fp32 -> (bf16 hi, bf16 lo) split
// ---------------------------------------------------------------------------
__global__ __launch_bounds__(256) void split_bf16(
    const float4* __restrict__ x, uint2* __restrict__ h, uint2* __restrict__ l, int n4)
{
    int i = blockIdx.x * 256 + threadIdx.x;
    if (i >= n4) return;
    float4 v = x[i];
    union { __nv_bfloat16 b[4]; uint2 u; } H, L;
    H.b[0] = __float2bfloat16(v.x);
    H.b[1] = __float2bfloat16(v.y);
    H.b[2] = __float2bfloat16(v.z);
    H.b[3] = __float2bfloat16(v.w);
    L.b[0] = __float2bfloat16(v.x - __bfloat162float(H.b[0]));
    L.b[1] = __float2bfloat16(v.y - __bfloat162float(H.b[1]));
    L.b[2] = __float2bfloat16(v.z - __bfloat162float(H.b[2]));
    L.b[3] = __float2bfloat16(v.w - __bfloat162float(H.b[3]));
    h[i] = H.u;
    l[i] = L.u;
}

// ---------------------------------------------------------------------------
// cp.async double-buffered mma.sync bf16x3 GEMM.
// C = (Ah+Al)[M,K] @ (Bh+Bl)[N,K]^T + bias;  D += Ah*Bh + Ah*Bl + Al*Bh.
// Output: fp32 C (if CH==null) or bf16 hi/lo pair CH/CL.
// 128x128x32 tile, 256 threads, warp tile 64x32.
// ---------------------------------------------------------------------------
#define BM 128
#define BN 128
#define BK 32
#define LDT 40
#define TSZ (128*LDT)
#define STG (4*TSZ)                 // one stage, bf16 units
#define GEMM_SMEM (2*STG*2)         // 81920 bytes

__device__ __forceinline__ void gemm_issue(
    const __nv_bfloat16* s0, const __nv_bfloat16* s1,
    const __nv_bfloat16* s2, const __nv_bfloat16* s3,
    int kc, uint32_t sstage, int tid)
{
    const __nv_bfloat16* src[4] = { s0, s1, s2, s3 };
#pragma unroll
    for (int t = 0; t < 4; t++) {
#pragma unroll
        for (int j = 0; j < 2; j++) {
            int idx = tid + j * 256;
            int r = idx >> 2, c = (idx & 3) * 8;
            CP_ASYNC16(sstage + (t * TSZ + r * LDT + c) * 2,
                       src[t] + (size_t)r * DIM + kc * BK + c);
        }
    }
}

__global__ __launch_bounds__(256, 2) void gemm_mma_bf16x3(
    const __nv_bfloat16* __restrict__ Ah, const __nv_bfloat16* __restrict__ Al,
    const __nv_bfloat16* __restrict__ Bh, const __nv_bfloat16* __restrict__ Bl,
    const float* __restrict__ bias, float* __restrict__ C,
    __nv_bfloat16* __restrict__ CH, __nv_bfloat16* __restrict__ CL)
{
    extern __shared__ __nv_bfloat16 smb[];
    const int tid = threadIdx.x, wid = tid >> 5, lane = tid & 31;
    const int bm = blockIdx.y * BM, bn = blockIdx.x * BN;
    const int wm = (wid & 1) * 64, wn = (wid >> 1) * 32;

    const __nv_bfloat16* sA0 = Ah + (size_t)bm * DIM;
    const __nv_bfloat16* sA1 = Al + (size_t)bm * DIM;
    const __nv_bfloat16* sB0 = Bh + (size_t)bn * DIM;
    const __nv_bfloat16* sB1 = Bl + (size_t)bn * DIM;

    float acc[4][4][4];
#pragma unroll
    for (int i = 0; i < 4; i++)
#pragma unroll
        for (int j = 0; j < 4; j++)
#pragma unroll
            for (int k = 0; k < 4; k++) acc[i][j][k] = 0.0f;

    const int seg = lane >> 3, lr = lane & 7;
    const int a_row = wm + (seg & 1) * 8 + lr;
    const int a_kof = (seg >> 1) * 8;
    const int b_row = wn + lr;
    const int b_kof = (seg & 1) * 8;

    const uint32_t sb = smem_u32(smb);
    const uint32_t oAh = (a_row * LDT + a_kof) * 2;
    const uint32_t oAl = oAh + TSZ * 2;
    const uint32_t oBh = ((b_row * LDT + b_kof) + 2 * TSZ) * 2;
    const uint32_t oBl = oBh + TSZ * 2;

    // prologue: stages 0,1
    gemm_issue(sA0, sA1, sB0, sB1, 0, sb, tid);             CP_COMMIT();
    gemm_issue(sA0, sA1, sB0, sB1, 1, sb + STG * 2, tid);   CP_COMMIT();

    for (int kc = 0; kc < DIM / BK; kc++) {
        CP_WAIT1();
        __syncthreads();
        const uint32_t st = sb + (kc & 1) * (STG * 2);

#pragma unroll
        for (int ks = 0; ks < 2; ks++) {
            const uint32_t ko = ks * 32;
            uint32_t bh[4][2], bl[4][2];
#pragma unroll
            for (int nt = 0; nt < 4; nt++) {
                uint32_t ad = st + nt * (8 * LDT * 2) + ko;
                asm volatile("ldmatrix.sync.aligned.m8n8.x2.shared.b16 {%0,%1}, [%2];"
                    : "=r"(bh[nt][0]), "=r"(bh[nt][1]) : "r"(ad + oBh));
                asm volatile("ldmatrix.sync.aligned.m8n8.x2.shared.b16 {%0,%1}, [%2];"
                    : "=r"(bl[nt][0]), "=r"(bl[nt][1]) : "r"(ad + oBl));
            }
#pragma unroll
            for (int mt = 0; mt < 4; mt++) {
                uint32_t ah[4], al[4];
                uint32_t ad = st + mt * (16 * LDT * 2) + ko;
                ldsm4(ah, ad + oAh);
                ldsm4(al, ad + oAl);
#pragma unroll
                for (int nt = 0; nt < 4; nt++) {
                    mma16816(acc[mt][nt], ah, bh[nt]);
                    mma16816(acc[mt][nt], ah, bl[nt]);
                    mma16816(acc[mt][nt], al, bh[nt]);
                }
            }
        }
        __syncthreads();
        if (kc + 2 < DIM / BK)
            gemm_issue(sA0, sA1, sB0, sB1, kc + 2, sb + ((kc + 2) & 1) * (STG * 2), tid);
        CP_COMMIT();
    }

    // Epilogue
    const int gr = lane >> 2, gc = (lane & 3) * 2;
#pragma unroll
    for (int mt = 0; mt < 4; mt++) {
#pragma unroll
        for (int nt = 0; nt < 4; nt++) {
            int col  = bn + wn + nt * 8 + gc;
            float b0 = bias[col], b1 = bias[col + 1];
            size_t r0 = (size_t)(bm + wm + mt * 16 + gr) * DIM + col;
            size_t r1 = r0 + 8 * DIM;
            float v0 = acc[mt][nt][0] + b0, v1 = acc[mt][nt][1] + b1;
            float v2 = acc[mt][nt][2] + b0, v3 = acc[mt][nt][3] + b1;
            if (CH) {
                uint32_t h0 = packbf(v1, v0);
                uint32_t l0 = packbf(v1 - bfhi(h0), v0 - bflo(h0));
                uint32_t h1 = packbf(v3, v2);
                uint32_t l1 = packbf(v3 - bfhi(h1), v2 - bflo(h1));
                *(uint32_t*)&CH[r0] = h0; *(uint32_t*)&CL[r0] = l0;
                *(uint32_t*)&CH[r1] = h1; *(uint32_t*)&CL[r1] = l1;
            } else {
                float2 w0 = { v0, v1 }, w1 = { v2, v3 };
                *(float2*)&C[r0] = w0;
                *(float2*)&C[r1] = w1;
            }
        }
    }
}

// ---------------------------------------------------------------------------
// Tensor-core flash attention (bf16x3 QK^T, bf16x3 PV, fp32 softmax).
// Block: 128 t rows x one (b,h); f loop in 128-tiles. 8 warps, warp = 16 t rows.
// ---------------------------------------------------------------------------
#define ALD 72
#define SQH 0
#define SQL 9216
#define SKH 18432
#define SKL 27648
#define SVH 36864
#define SVL 46080
#define ATT_SMEM (55296*2)

__global__ __launch_bounds__(256, 1) void attn_mma(
    const __nv_bfloat16* __restrict__ QH, const __nv_bfloat16* __restrict__ QL,
    const __nv_bfloat16* __restrict__ KH, const __nv_bfloat16* __restrict__ KL,
    const __nv_bfloat16* __restrict__ VH, const __nv_bfloat16* __restrict__ VL,
    const int* __restrict__ mask,
    __nv_bfloat16* __restrict__ AHo, __nv_bfloat16* __restrict__ ALo)
{
    extern __shared__ __nv_bfloat16 sm[];
    const int tid = threadIdx.x, w = tid >> 5, lane = tid & 31;
    const int t0 = blockIdx.x * 128, h = blockIdx.y, b = blockIdx.z;
    const int lr = lane & 7, seg = lane >> 3;
    const int gr = lane >> 2, qc = (lane & 3) * 2;
    const uint32_t sb = smem_u32(sm);

    // Load Q tile (hi/lo)
    {
        const size_t grow = (size_t)(b * GT + t0);
#pragma unroll
        for (int j = 0; j < 4; j++) {
            int idx = tid + j * 256;
            int r = idx >> 3, c = (idx & 7) * 8;
            size_t g = (grow + r) * DIM + h * HD + c;
            *(uint4*)&sm[SQH + r * ALD + c] = *(const uint4*)&QH[g];
            *(uint4*)&sm[SQL + r * ALD + c] = *(const uint4*)&QL[g];
        }
    }
    __syncthreads();

    // Q A-fragments (resident)
    uint32_t qh[4][4], ql[4][4];
#pragma unroll
    for (int kc = 0; kc < 4; kc++) {
        uint32_t ad = sb + ((w * 16 + (seg & 1) * 8 + lr) * ALD + kc * 16 + (seg >> 1) * 8) * 2;
        ldsm4(qh[kc], ad + SQH * 2);
        ldsm4(ql[kc], ad + SQL * 2);
    }

    float oacc[8][4];
#pragma unroll
    for (int i = 0; i < 8; i++)
#pragma unroll
        for (int j = 0; j < 4; j++) oacc[i][j] = 0.0f;
    float m0 = -1e30f, m1 = -1e30f, l0 = 0.0f, l1 = 0.0f;

    const int mrow0 = b * GT + t0 + w * 16 + gr;

    for (int ftile = 0; ftile < 8; ftile++) {
        const int f0 = ftile * 128;
        __syncthreads();
        // Load K,V tiles (hi/lo), [f][d] layout
        {
            const size_t gfrow = (size_t)(b * GF + f0);
#pragma unroll
            for (int j = 0; j < 4; j++) {
                int idx = tid + j * 256;
                int r = idx >> 3, c = (idx & 7) * 8;
                size_t g = (gfrow + r) * DIM + h * HD + c;
                uint32_t so = r * ALD + c;
                *(uint4*)&sm[SKH + so] = *(const uint4*)&KH[g];
                *(uint4*)&sm[SKL + so] = *(const uint4*)&KL[g];
                *(uint4*)&sm[SVH + so] = *(const uint4*)&VH[g];
                *(uint4*)&sm[SVL + so] = *(const uint4*)&VL[g];
            }
        }
        __syncthreads();

        // S = Q K^T (bf16x3)
        float sacc[16][4];
#pragma unroll
        for (int nt = 0; nt < 16; nt++) {
#pragma unroll
            for (int j = 0; j < 4; j++) sacc[nt][j] = 0.0f;
        }
#pragma unroll
        for (int nt = 0; nt < 16; nt++) {
            uint32_t bh[8], bl[8];
#pragma unroll
            for (int kcg = 0; kcg < 2; kcg++) {
                uint32_t ad = sb + ((nt * 8 + lr) * ALD + kcg * 32 + seg * 8) * 2;
                ldsm4(&bh[kcg * 4], ad + SKH * 2);
                ldsm4(&bl[kcg * 4], ad + SKL * 2);
            }
#pragma unroll
            for (int kc = 0; kc < 4; kc++) {
                mma16816(sacc[nt], qh[kc], &bh[kc * 2]);
                mma16816(sacc[nt], qh[kc], &bl[kc * 2]);
                mma16816(sacc[nt], ql[kc], &bh[kc * 2]);
            }
        }

        // mask + scale + row max
        float rm0 = -1e30f, rm1 = -1e30f;
#pragma unroll
        for (int nt = 0; nt < 16; nt++) {
            int fcol = f0 + nt * 8 + qc;
            int2 mA = *(const int2*)&mask[(size_t)mrow0 * GF + fcol];
            int2 mB = *(const int2*)&mask[(size_t)(mrow0 + 8) * GF + fcol];
            float s0 = mA.x ? sacc[nt][0] * 0.125f : -10000.0f;
            float s1 = mA.y ? sacc[nt][1] * 0.125f : -10000.0f;
            float s2 = mB.x ? sacc[nt][2] * 0.125f : -10000.0f;
            float s3 = mB.y ? sacc[nt][3] * 0.125f : -10000.0f;
            sacc[nt][0] = s0; sacc[nt][1] = s1; sacc[nt][2] = s2; sacc[nt][3] = s3;
            rm0 = fmaxf(rm0, fmaxf(s0, s1));
            rm1 = fmaxf(rm1, fmaxf(s2, s3));
        }
        rm0 = fmaxf(rm0, __shfl_xor_sync(0xffffffffu, rm0, 1));
        rm0 = fmaxf(rm0, __shfl_xor_sync(0xffffffffu, rm0, 2));
        rm1 = fmaxf(rm1, __shfl_xor_sync(0xffffffffu, rm1, 1));
        rm1 = fmaxf(rm1, __shfl_xor_sync(0xffffffffu, rm1, 2));
        float mn0 = fmaxf(m0, rm0), mn1 = fmaxf(m1, rm1);
        float c0 = fast_exp(m0 - mn0), c1 = fast_exp(m1 - mn1);
        m0 = mn0; m1 = mn1;

        // P = exp(s-m), pack A-frags hi/lo, row sums
        uint32_t pah[8][4], pal[8][4];
        float rs0 = 0.0f, rs1 = 0.0f;
#pragma unroll
        for (int kc = 0; kc < 8; kc++) {
            float p0 = fast_exp(sacc[2*kc][0] - m0);
            float p1 = fast_exp(sacc[2*kc][1] - m0);
            float p2 = fast_exp(sacc[2*kc][2] - m1);
            float p3 = fast_exp(sacc[2*kc][3] - m1);
            float p4 = fast_exp(sacc[2*kc+1][0] - m0);
            float p5 = fast_exp(sacc[2*kc+1][1] - m0);
            float p6 = fast_exp(sacc[2*kc+1][2] - m1);
            float p7 = fast_exp(sacc[2*kc+1][3] - m1);
            rs0 += (p0 + p1) + (p4 + p5);
            rs1 += (p2 + p3) + (p6 + p7);
            uint32_t h0 = packbf(p1, p0), h1 = packbf(p3, p2);
            uint32_t h2 = packbf(p5, p4), h3 = packbf(p7, p6);
            pah[kc][0] = h0; pah[kc][1] = h1; pah[kc][2] = h2; pah[kc][3] = h3;
            pal[kc][0] = packbf(p1 - bfhi(h0), p0 - bflo(h0));
            pal[kc][1] = packbf(p3 - bfhi(h1), p2 - bflo(h1));
            pal[kc][2] = packbf(p5 - bfhi(h2), p4 - bflo(h2));
            pal[kc][3] = packbf(p7 - bfhi(h3), p6 - bflo(h3));
        }
        rs0 += __shfl_xor_sync(0xffffffffu, rs0, 1);
        rs0 += __shfl_xor_sync(0xffffffffu, rs0, 2);
        rs1 += __shfl_xor_sync(0xffffffffu, rs1, 1);
        rs1 += __shfl_xor_sync(0xffffffffu, rs1, 2);
        l0 = l0 * c0 + rs0;
        l1 = l1 * c1 + rs1;

        // rescale O
#pragma unroll
        for (int nt = 0; nt < 8; nt++) {
            oacc[nt][0] *= c0; oacc[nt][1] *= c0;
            oacc[nt][2] *= c1; oacc[nt][3] *= c1;
        }

        // O += P V (bf16x3)
#pragma unroll
        for (int kcg = 0; kcg < 4; kcg++) {
#pragma unroll
            for (int nt = 0; nt < 8; nt++) {
                uint32_t bvh[4], bvl[4];
                uint32_t ad = sb + ((kcg * 32 + seg * 8 + lr) * ALD + nt * 8) * 2;
                ldsm4t(bvh, ad + SVH * 2);
                ldsm4t(bvl, ad + SVL * 2);
                mma16816(oacc[nt], pah[2*kcg],     bvh);
                mma16816(oacc[nt], pal[2*kcg],     bvh);
                mma16816(oacc[nt], pah[2*kcg],     bvl);
                mma16816(oacc[nt], pah[2*kcg+1],   &bvh[2]);
                mma16816(oacc[nt], pal[2*kcg+1],   &bvh[2]);
                mma16816(oacc[nt], pah[2*kcg+1],   &bvl[2]);
            }
        }
    }

    // Epilogue: normalize, write bf16 hi/lo
    float inv0 = 1.0f / l0, inv1 = 1.0f / l1;
    size_t orow = (size_t)(b * GT + t0 + w * 16 + gr) * DIM + h * HD;
#pragma unroll
    for (int nt = 0; nt < 8; nt++) {
        int col = nt * 8 + qc;
        float v0 = oacc[nt][0] * inv0, v1 = oacc[nt][1] * inv0;
        float v2 = oacc[nt][2] * inv1, v3 = oacc[nt][3] * inv1;
        uint32_t h0 = packbf(v1, v0);
        uint32_t l0p = packbf(v1 - bfhi(h0), v0 - bflo(h0));
        uint32_t h1 = packbf(v3, v2);
        uint32_t l1p = packbf(v3 - bfhi(h1), v2 - bflo(h1));
        *(uint32_t*)&AHo[orow + col] = h0;
        *(uint32_t*)&ALo[orow + col] = l0p;
        *(uint32_t*)&AHo[orow + 8 * DIM + col] = h1;
        *(uint32_t*)&ALo[orow + 8 * DIM + col] = l1p;
    }
}

// ---------------------------------------------------------------------------
// Launch
// ---------------------------------------------------------------------------
extern "C" void kernel_launch(void* const* d_in, const int* in_sizes, int n_in,
                              void* d_out, int out_size)
{
    const float* X_to   = (const float*)d_in[0];
    const float* X_from = (const float*)d_in[1];
    const int*   maskp  = (const int*)  d_in[2];
    const float* Wq = (const float*)d_in[3];
    const float* bq = (const float*)d_in[4];
    const float* Wk = (const float*)d_in[5];
    const float* bk = (const float*)d_in[6];
    const float* Wv = (const float*)d_in[7];
    const float* bv = (const float*)d_in[8];
    const float* Wo = (const float*)d_in[9];
    const float* bo = (const float*)d_in[10];
    float* out = (float*)d_out;

    __nv_bfloat16 *QH,*QL,*KH,*KL,*VH,*VL,*AH,*AL;
    __nv_bfloat16 *XtH,*XtL,*XfH,*XfL;
    __nv_bfloat16 *WqH,*WqL,*WkH,*WkL,*WvH,*WvL,*WoH,*WoL;
    cudaGetSymbolAddress((void**)&QH, g_QH); cudaGetSymbolAddress((void**)&QL, g_QL);
    cudaGetSymbolAddress((void**)&KH, g_KH); cudaGetSymbolAddress((void**)&KL, g_KL);
    cudaGetSymbolAddress((void**)&VH, g_VH); cudaGetSymbolAddress((void**)&VL, g_VL);
    cudaGetSymbolAddress((void**)&AH, g_AH); cudaGetSymbolAddress((void**)&AL, g_AL);
    cudaGetSymbolAddress((void**)&XtH, g_XtH); cudaGetSymbolAddress((void**)&XtL, g_XtL);
    cudaGetSymbolAddress((void**)&XfH, g_XfH); cudaGetSymbolAddress((void**)&XfL, g_XfL);
    cudaGetSymbolAddress((void**)&WqH, g_WqH); cudaGetSymbolAddress((void**)&WqL, g_WqL);
    cudaGetSymbolAddress((void**)&WkH, g_WkH); cudaGetSymbolAddress((void**)&WkL, g_WkL);
    cudaGetSymbolAddress((void**)&WvH, g_WvH); cudaGetSymbolAddress((void**)&WvL, g_WvL);
    cudaGetSymbolAddress((void**)&WoH, g_WoH); cudaGetSymbolAddress((void**)&WoL, g_WoL);

    cudaFuncSetAttribute(gemm_mma_bf16x3,
                         cudaFuncAttributeMaxDynamicSharedMemorySize, GEMM_SMEM);
    cudaFuncSetAttribute(attn_mma,
                         cudaFuncAttributeMaxDynamicSharedMemorySize, ATT_SMEM);

    const int nX4 = MTOT * DIM / 4;
    const int nW4 = DIM * DIM / 4;

    split_bf16<<<nX4 / 256, 256>>>((const float4*)X_to,   (uint2*)XtH, (uint2*)XtL, nX4);
    split_bf16<<<nX4 / 256, 256>>>((const float4*)X_from, (uint2*)XfH, (uint2*)XfL, nX4);
    split_bf16<<<nW4 / 256, 256>>>((const float4*)Wq, (uint2*)WqH, (uint2*)WqL, nW4);
    split_bf16<<<nW4 / 256, 256>>>((const float4*)Wk, (uint2*)WkH, (uint2*)WkL, nW4);
    split_bf16<<<nW4 / 256, 256>>>((const float4*)Wv, (uint2*)WvH, (uint2*)WvL, nW4);
    split_bf16<<<nW4 / 256, 256>>>((const float4*)Wo, (uint2*)WoH, (uint2*)WoL, nW4);

    dim3 gg(DIM / BN, MTOT / BM);   // (8, 32)

    // Projections -> bf16 hi/lo pairs. NOTE reference's swap: K<=Wv/bv, V<=Wk/bk.
    gemm_mma_bf16x3<<<gg, 256, GEMM_SMEM>>>(XtH, XtL, WqH, WqL, bq, nullptr, QH, QL);
    gemm_mma_bf16x3<<<gg, 256, GEMM_SMEM>>>(XfH, XfL, WvH, WvL, bv, nullptr, KH, KL);
    gemm_mma_bf16x3<<<gg, 256, GEMM_SMEM>>>(XfH, XfL, WkH, WkL, bk, nullptr, VH, VL);

    dim3 ag(GT / 128, GH, GB);      // (8, 16, 4)
    attn_mma<<<ag, 256, ATT_SMEM>>>(QH, QL, KH, KL, VH, VL, maskp, AH, AL);

    // Output projection (fp32 out)
    gemm_mma_bf16x3<<<gg, 256, GEMM_SMEM>>>(AH, AL, WoH, WoL, bo, out, nullptr, nullptr);
}

// round 5
// speedup vs baseline: 2.4722x; 1.0233x over previous
#include <cuda_runtime.h>
#include <cuda_bf16.h>
#include <cstdint>
#include <math.h>

// Problem constants
#define GB 4
#define GT 1024
#define GF 1024
#define DIM 1024
#define GH 16
#define HD 64
#define MTOT (GB*GT)   // 4096

// ---------------------------------------------------------------------------
// Scratch (__device__ globals; allocation-free rule)
// ---------------------------------------------------------------------------
__device__ __nv_bfloat16 g_QH[MTOT*DIM], g_QL[MTOT*DIM];
__device__ __nv_bfloat16 g_KH[MTOT*DIM], g_KL[MTOT*DIM];
__device__ __nv_bfloat16 g_VH[MTOT*DIM], g_VL[MTOT*DIM];
__device__ __nv_bfloat16 g_AH[MTOT*DIM], g_AL[MTOT*DIM];
__device__ __nv_bfloat16 g_XtH[MTOT*DIM], g_XtL[MTOT*DIM];
__device__ __nv_bfloat16 g_XfH[MTOT*DIM], g_XfL[MTOT*DIM];
__device__ __nv_bfloat16 g_WqH[DIM*DIM],  g_WqL[DIM*DIM];
__device__ __nv_bfloat16 g_WkH[DIM*DIM],  g_WkL[DIM*DIM];
__device__ __nv_bfloat16 g_WvH[DIM*DIM],  g_WvL[DIM*DIM];
__device__ __nv_bfloat16 g_WoH[DIM*DIM],  g_WoL[DIM*DIM];
__device__ uint32_t g_mbits[MTOT*GF/32];   // bit-packed mask, 512KB

// ---------------------------------------------------------------------------
// Helpers
// ---------------------------------------------------------------------------
__device__ __forceinline__ uint32_t smem_u32(const void* p){
    uint32_t a;
    asm("{ .reg .u64 t; cvta.to.shared.u64 t, %1; cvt.u32.u64 %0, t; }"
        : "=r"(a) : "l"(p));
    return a;
}
__device__ __forceinline__ void ldsm4(uint32_t* r, uint32_t addr){
    asm volatile("ldmatrix.sync.aligned.m8n8.x4.shared.b16 {%0,%1,%2,%3}, [%4];"
        : "=r"(r[0]), "=r"(r[1]), "=r"(r[2]), "=r"(r[3]) : "r"(addr));
}
__device__ __forceinline__ void ldsm4t(uint32_t* r, uint32_t addr){
    asm volatile("ldmatrix.sync.aligned.m8n8.x4.trans.shared.b16 {%0,%1,%2,%3}, [%4];"
        : "=r"(r[0]), "=r"(r[1]), "=r"(r[2]), "=r"(r[3]) : "r"(addr));
}
__device__ __forceinline__ void mma16816(float* d, const uint32_t* a, const uint32_t* b){
    asm volatile("mma.sync.aligned.m16n8k16.row.col.f32.bf16.bf16.f32 "
        "{%0,%1,%2,%3}, {%4,%5,%6,%7}, {%8,%9}, {%0,%1,%2,%3};"
        : "+f"(d[0]), "+f"(d[1]), "+f"(d[2]), "+f"(d[3])
        : "r"(a[0]), "r"(a[1]), "r"(a[2]), "r"(a[3]), "r"(b[0]), "r"(b[1]));
}
__device__ __forceinline__ uint32_t packbf(float hi, float lo){
    uint32_t r;
    asm("cvt.rn.bf16x2.f32 %0, %1, %2;" : "=r"(r) : "f"(hi), "f"(lo));
    return r;
}
__device__ __forceinline__ float bflo(uint32_t r){ return __int_as_float(r << 16); }
__device__ __forceinline__ float bfhi(uint32_t r){ return __int_as_float(r & 0xFFFF0000u); }

// Branch-free exp on FMA/ALU pipes only.
__device__ __forceinline__ float fast_exp(float x){
    float xc = fmaxf(x, -87.0f);
    float r  = fmaf(xc, 1.4426950408889634f, 12582912.0f);
    int   n  = __float_as_int(r) - 0x4B400000;
    float fi = r - 12582912.0f;
    float g  = fmaf(fi, -0.6931471805599453f, xc);
    float p  = 8.3333337e-3f;
    p = fmaf(p, g, 4.1666668e-2f);
    p = fmaf(p, g, 1.6666667e-1f);
    p = fmaf(p, g, 0.5f);
    p = fmaf(p, g, 1.0f);
    p = fmaf(p, g, 1.0f);
    return p * __int_as_float((n << 23) + 0x3F800000);
}

#define CP_ASYNC16(sm, gp) \
    asm volatile("cp.async.cg.shared.global [%0], [%1], 16;" :: "r"(sm), "l"(gp))
#define CP_COMMIT() asm volatile("cp.async.commit_group;")
#define CP_WAIT1()  asm volatile("cp.async.wait_group 1;")

// ---------------------------------------------------------------------------
// fp32 -> (bf16 hi, bf16 lo) split
// ---------------------------------------------------------------------------
__global__ __launch_bounds__(256) void split_bf16(
    const float4* __restrict__ x, uint2* __restrict__ h, uint2* __restrict__ l, int n4)
{
    int i = blockIdx.x * 256 + threadIdx.x;
    if (i >= n4) return;
    float4 v = x[i];
    union { __nv_bfloat16 b[4]; uint2 u; } H, L;
    H.b[0] = __float2bfloat16(v.x);
    H.b[1] = __float2bfloat16(v.y);
    H.b[2] = __float2bfloat16(v.z);
    H.b[3] = __float2bfloat16(v.w);
    L.b[0] = __float2bfloat16(v.x - __bfloat162float(H.b[0]));
    L.b[1] = __float2bfloat16(v.y - __bfloat162float(H.b[1]));
    L.b[2] = __float2bfloat16(v.z - __bfloat162float(H.b[2]));
    L.b[3] = __float2bfloat16(v.w - __bfloat162float(H.b[3]));
    h[i] = H.u;
    l[i] = L.u;
}

// mask int32 -> bit-packed (bit f%32 of word (row*GF+f)/32)
__global__ __launch_bounds__(256) void pack_mask(
    const int* __restrict__ m, uint32_t* __restrict__ bits)
{
    int i = blockIdx.x * 256 + threadIdx.x;
    unsigned v = __ballot_sync(0xffffffffu, m[i] != 0);
    if ((threadIdx.x & 31) == 0) bits[i >> 5] = v;
}

// ---------------------------------------------------------------------------
// cp.async double-buffered mma.sync bf16x3 GEMM (unchanged from R4).
// ---------------------------------------------------------------------------
#define BM 128
#define BN 128
#define BK 32
#define LDT 40
#define TSZ (128*LDT)
#define STG (4*TSZ)
#define GEMM_SMEM (2*STG*2)

__device__ __forceinline__ void gemm_issue(
    const __nv_bfloat16* s0, const __nv_bfloat16* s1,
    const __nv_bfloat16* s2, const __nv_bfloat16* s3,
    int kc, uint32_t sstage, int tid)
{
    const __nv_bfloat16* src[4] = { s0, s1, s2, s3 };
#pragma unroll
    for (int t = 0; t < 4; t++) {
#pragma unroll
        for (int j = 0; j < 2; j++) {
            int idx = tid + j * 256;
            int r = idx >> 2, c = (idx & 3) * 8;
            CP_ASYNC16(sstage + (t * TSZ + r * LDT + c) * 2,
                       src[t] + (size_t)r * DIM + kc * BK + c);
        }
    }
}

__global__ __launch_bounds__(256, 2) void gemm_mma_bf16x3(
    const __nv_bfloat16* __restrict__ Ah, const __nv_bfloat16* __restrict__ Al,
    const __nv_bfloat16* __restrict__ Bh, const __nv_bfloat16* __restrict__ Bl,
    const float* __restrict__ bias, float* __restrict__ C,
    __nv_bfloat16* __restrict__ CH, __nv_bfloat16* __restrict__ CL)
{
    extern __shared__ __nv_bfloat16 smb[];
    const int tid = threadIdx.x, wid = tid >> 5, lane = tid & 31;
    const int bm = blockIdx.y * BM, bn = blockIdx.x * BN;
    const int wm = (wid & 1) * 64, wn = (wid >> 1) * 32;

    const __nv_bfloat16* sA0 = Ah + (size_t)bm * DIM;
    const __nv_bfloat16* sA1 = Al + (size_t)bm * DIM;
    const __nv_bfloat16* sB0 = Bh + (size_t)bn * DIM;
    const __nv_bfloat16* sB1 = Bl + (size_t)bn * DIM;

    float acc[4][4][4];
#pragma unroll
    for (int i = 0; i < 4; i++)
#pragma unroll
        for (int j = 0; j < 4; j++)
#pragma unroll
            for (int k = 0; k < 4; k++) acc[i][j][k] = 0.0f;

    const int seg = lane >> 3, lr = lane & 7;
    const int a_row = wm + (seg & 1) * 8 + lr;
    const int a_kof = (seg >> 1) * 8;
    const int b_row = wn + lr;
    const int b_kof = (seg & 1) * 8;

    const uint32_t sb = smem_u32(smb);
    const uint32_t oAh = (a_row * LDT + a_kof) * 2;
    const uint32_t oAl = oAh + TSZ * 2;
    const uint32_t oBh = ((b_row * LDT + b_kof) + 2 * TSZ) * 2;
    const uint32_t oBl = oBh + TSZ * 2;

    gemm_issue(sA0, sA1, sB0, sB1, 0, sb, tid);             CP_COMMIT();
    gemm_issue(sA0, sA1, sB0, sB1, 1, sb + STG * 2, tid);   CP_COMMIT();

    for (int kc = 0; kc < DIM / BK; kc++) {
        CP_WAIT1();
        __syncthreads();
        const uint32_t st = sb + (kc & 1) * (STG * 2);

#pragma unroll
        for (int ks = 0; ks < 2; ks++) {
            const uint32_t ko = ks * 32;
            uint32_t bh[4][2], bl[4][2];
#pragma unroll
            for (int nt = 0; nt < 4; nt++) {
                uint32_t ad = st + nt * (8 * LDT * 2) + ko;
                asm volatile("ldmatrix.sync.aligned.m8n8.x2.shared.b16 {%0,%1}, [%2];"
                    : "=r"(bh[nt][0]), "=r"(bh[nt][1]) : "r"(ad + oBh));
                asm volatile("ldmatrix.sync.aligned.m8n8.x2.shared.b16 {%0,%1}, [%2];"
                    : "=r"(bl[nt][0]), "=r"(bl[nt][1]) : "r"(ad + oBl));
            }
#pragma unroll
            for (int mt = 0; mt < 4; mt++) {
                uint32_t ah[4], al[4];
                uint32_t ad = st + mt * (16 * LDT * 2) + ko;
                ldsm4(ah, ad + oAh);
                ldsm4(al, ad + oAl);
#pragma unroll
                for (int nt = 0; nt < 4; nt++) {
                    mma16816(acc[mt][nt], ah, bh[nt]);
                    mma16816(acc[mt][nt], ah, bl[nt]);
                    mma16816(acc[mt][nt], al, bh[nt]);
                }
            }
        }
        __syncthreads();
        if (kc + 2 < DIM / BK)
            gemm_issue(sA0, sA1, sB0, sB1, kc + 2, sb + ((kc + 2) & 1) * (STG * 2), tid);
        CP_COMMIT();
    }

    const int gr = lane >> 2, gc = (lane & 3) * 2;
#pragma unroll
    for (int mt = 0; mt < 4; mt++) {
#pragma unroll
        for (int nt = 0; nt < 4; nt++) {
            int col  = bn + wn + nt * 8 + gc;
            float b0 = bias[col], b1 = bias[col + 1];
            size_t r0 = (size_t)(bm + wm + mt * 16 + gr) * DIM + col;
            size_t r1 = r0 + 8 * DIM;
            float v0 = acc[mt][nt][0] + b0, v1 = acc[mt][nt][1] + b1;
            float v2 = acc[mt][nt][2] + b0, v3 = acc[mt][nt][3] + b1;
            if (CH) {
                uint32_t h0 = packbf(v1, v0);
                uint32_t l0 = packbf(v1 - bfhi(h0), v0 - bflo(h0));
                uint32_t h1 = packbf(v3, v2);
                uint32_t l1 = packbf(v3 - bfhi(h1), v2 - bflo(h1));
                *(uint32_t*)&CH[r0] = h0; *(uint32_t*)&CL[r0] = l0;
                *(uint32_t*)&CH[r1] = h1; *(uint32_t*)&CL[r1] = l1;
            } else {
                float2 w0 = { v0, v1 }, w1 = { v2, v3 };
                *(float2*)&C[r0] = w0;
                *(float2*)&C[r1] = w1;
            }
        }
    }
}

// ---------------------------------------------------------------------------
// Tensor-core flash attention with cp.async double-buffered K/V + bitmask.
// ---------------------------------------------------------------------------
#define ALD 72
#define SQH 0
#define SQL 9216
#define SKV0 18432
#define KVSTG 36864          // bf16 units per stage (KH,KL,VH,VL @ 9216 each)
#define ATT_SMEM ((SKV0 + 2*KVSTG)*2)   // 184320 bytes

__device__ __forceinline__ void kv_issue(
    const __nv_bfloat16* KH, const __nv_bfloat16* KL,
    const __nv_bfloat16* VH, const __nv_bfloat16* VL,
    size_t gfrow, int hof, uint32_t stbase, int tid)
{
#pragma unroll
    for (int j = 0; j < 4; j++) {
        int idx = tid + j * 256;
        int r = idx >> 3, c = (idx & 7) * 8;
        size_t g = (gfrow + r) * DIM + hof + c;
        uint32_t so = stbase + (r * ALD + c) * 2;
        CP_ASYNC16(so,               KH + g);
        CP_ASYNC16(so +  9216 * 2,   KL + g);
        CP_ASYNC16(so + 18432 * 2,   VH + g);
        CP_ASYNC16(so + 27648 * 2,   VL + g);
    }
}

__global__ __launch_bounds__(256, 1) void attn_mma(
    const __nv_bfloat16* __restrict__ QH, const __nv_bfloat16* __restrict__ QL,
    const __nv_bfloat16* __restrict__ KH, const __nv_bfloat16* __restrict__ KL,
    const __nv_bfloat16* __restrict__ VH, const __nv_bfloat16* __restrict__ VL,
    const uint32_t* __restrict__ mbits,
    __nv_bfloat16* __restrict__ AHo, __nv_bfloat16* __restrict__ ALo)
{
    extern __shared__ __nv_bfloat16 sm[];
    const int tid = threadIdx.x, w = tid >> 5, lane = tid & 31;
    const int t0 = blockIdx.x * 128, h = blockIdx.y, b = blockIdx.z;
    const int lr = lane & 7, seg = lane >> 3;
    const int gr = lane >> 2, qc = (lane & 3) * 2;
    const uint32_t sb = smem_u32(sm);
    const int hof = h * HD;
    const size_t gfbase = (size_t)(b * GF);

    // prefetch KV stage 0
    kv_issue(KH, KL, VH, VL, gfbase, hof, sb + SKV0 * 2, tid);
    CP_COMMIT();

    // Load Q tile (hi/lo), regular loads
    {
        const size_t grow = (size_t)(b * GT + t0);
#pragma unroll
        for (int j = 0; j < 4; j++) {
            int idx = tid + j * 256;
            int r = idx >> 3, c = (idx & 7) * 8;
            size_t g = (grow + r) * DIM + hof + c;
            *(uint4*)&sm[SQH + r * ALD + c] = *(const uint4*)&QH[g];
            *(uint4*)&sm[SQL + r * ALD + c] = *(const uint4*)&QL[g];
        }
    }
    __syncthreads();

    uint32_t qh[4][4], ql[4][4];
#pragma unroll
    for (int kc = 0; kc < 4; kc++) {
        uint32_t ad = sb + ((w * 16 + (seg & 1) * 8 + lr) * ALD + kc * 16 + (seg >> 1) * 8) * 2;
        ldsm4(qh[kc], ad + SQH * 2);
        ldsm4(ql[kc], ad + SQL * 2);
    }

    float oacc[8][4];
#pragma unroll
    for (int i = 0; i < 8; i++)
#pragma unroll
        for (int j = 0; j < 4; j++) oacc[i][j] = 0.0f;
    float m0 = -1e30f, m1 = -1e30f, l0 = 0.0f, l1 = 0.0f;

    const int mrow0 = b * GT + t0 + w * 16 + gr;
    const uint32_t* mrp0 = mbits + (size_t)mrow0 * (GF / 32);
    const uint32_t* mrp1 = mrp0 + 8 * (GF / 32);

    for (int ftile = 0; ftile < 8; ftile++) {
        __syncthreads();   // all warps done with the other stage
        if (ftile + 1 < 8)
            kv_issue(KH, KL, VH, VL, gfbase + (ftile + 1) * 128, hof,
                     sb + (SKV0 + ((ftile + 1) & 1) * KVSTG) * 2, tid);
        CP_COMMIT();
        CP_WAIT1();        // stage (ftile&1) complete
        __syncthreads();

        const uint32_t stg = SKV0 + (ftile & 1) * KVSTG;

        // mask bits for this tile (2 x uint4 = 256 bits)
        uint4 mw0 = *(const uint4*)(mrp0 + ftile * 4);
        uint4 mw1 = *(const uint4*)(mrp1 + ftile * 4);
        uint32_t wA[4] = { mw0.x, mw0.y, mw0.z, mw0.w };
        uint32_t wB[4] = { mw1.x, mw1.y, mw1.z, mw1.w };

        // S = Q K^T (bf16x3)
        float sacc[16][4];
#pragma unroll
        for (int nt = 0; nt < 16; nt++) {
#pragma unroll
            for (int j = 0; j < 4; j++) sacc[nt][j] = 0.0f;
        }
#pragma unroll
        for (int nt = 0; nt < 16; nt++) {
            uint32_t bh[8], bl[8];
#pragma unroll
            for (int kcg = 0; kcg < 2; kcg++) {
                uint32_t ad = sb + (stg + (nt * 8 + lr) * ALD + kcg * 32 + seg * 8) * 2;
                ldsm4(&bh[kcg * 4], ad);
                ldsm4(&bl[kcg * 4], ad + 9216 * 2);
            }
#pragma unroll
            for (int kc = 0; kc < 4; kc++) {
                mma16816(sacc[nt], qh[kc], &bh[kc * 2]);
                mma16816(sacc[nt], qh[kc], &bl[kc * 2]);
                mma16816(sacc[nt], ql[kc], &bh[kc * 2]);
            }
        }

        // mask + scale + row max
        float rm0 = -1e30f, rm1 = -1e30f;
#pragma unroll
        for (int nt = 0; nt < 16; nt++) {
            uint32_t sh = (nt & 3) * 8 + qc;
            uint32_t bA = wA[nt >> 2] >> sh;
            uint32_t bB = wB[nt >> 2] >> sh;
            float s0 = (bA & 1u) ? sacc[nt][0] * 0.125f : -10000.0f;
            float s1 = (bA & 2u) ? sacc[nt][1] * 0.125f : -10000.0f;
            float s2 = (bB & 1u) ? sacc[nt][2] * 0.125f : -10000.0f;
            float s3 = (bB & 2u) ? sacc[nt][3] * 0.125f : -10000.0f;
            sacc[nt][0] = s0; sacc[nt][1] = s1; sacc[nt][2] = s2; sacc[nt][3] = s3;
            rm0 = fmaxf(rm0, fmaxf(s0, s1));
            rm1 = fmaxf(rm1, fmaxf(s2, s3));
        }
        rm0 = fmaxf(rm0, __shfl_xor_sync(0xffffffffu, rm0, 1));
        rm0 = fmaxf(rm0, __shfl_xor_sync(0xffffffffu, rm0, 2));
        rm1 = fmaxf(rm1, __shfl_xor_sync(0xffffffffu, rm1, 1));
        rm1 = fmaxf(rm1, __shfl_xor_sync(0xffffffffu, rm1, 2));
        float mn0 = fmaxf(m0, rm0), mn1 = fmaxf(m1, rm1);
        float c0 = fast_exp(m0 - mn0), c1 = fast_exp(m1 - mn1);
        m0 = mn0; m1 = mn1;

        // P = exp(s-m), pack A-frags hi/lo, row sums
        uint32_t pah[8][4], pal[8][4];
        float rs0 = 0.0f, rs1 = 0.0f;
#pragma unroll
        for (int kc = 0; kc < 8; kc++) {
            float p0 = fast_exp(sacc[2*kc][0] - m0);
            float p1 = fast_exp(sacc[2*kc][1] - m0);
            float p2 = fast_exp(sacc[2*kc][2] - m1);
            float p3 = fast_exp(sacc[2*kc][3] - m1);
            float p4 = fast_exp(sacc[2*kc+1][0] - m0);
            float p5 = fast_exp(sacc[2*kc+1][1] - m0);
            float p6 = fast_exp(sacc[2*kc+1][2] - m1);
            float p7 = fast_exp(sacc[2*kc+1][3] - m1);
            rs0 += (p0 + p1) + (p4 + p5);
            rs1 += (p2 + p3) + (p6 + p7);
            uint32_t h0 = packbf(p1, p0), h1 = packbf(p3, p2);
            uint32_t h2 = packbf(p5, p4), h3 = packbf(p7, p6);
            pah[kc][0] = h0; pah[kc][1] = h1; pah[kc][2] = h2; pah[kc][3] = h3;
            pal[kc][0] = packbf(p1 - bfhi(h0), p0 - bflo(h0));
            pal[kc][1] = packbf(p3 - bfhi(h1), p2 - bflo(h1));
            pal[kc][2] = packbf(p5 - bfhi(h2), p4 - bflo(h2));
            pal[kc][3] = packbf(p7 - bfhi(h3), p6 - bflo(h3));
        }
        rs0 += __shfl_xor_sync(0xffffffffu, rs0, 1);
        rs0 += __shfl_xor_sync(0xffffffffu, rs0, 2);
        rs1 += __shfl_xor_sync(0xffffffffu, rs1, 1);
        rs1 += __shfl_xor_sync(0xffffffffu, rs1, 2);
        l0 = l0 * c0 + rs0;
        l1 = l1 * c1 + rs1;

#pragma unroll
        for (int nt = 0; nt < 8; nt++) {
            oacc[nt][0] *= c0; oacc[nt][1] *= c0;
            oacc[nt][2] *= c1; oacc[nt][3] *= c1;
        }

        // O += P V (bf16x3)
#pragma unroll
        for (int kcg = 0; kcg < 4; kcg++) {
#pragma unroll
            for (int nt = 0; nt < 8; nt++) {
                uint32_t bvh[4], bvl[4];
                uint32_t ad = sb + (stg + 18432 + (kcg * 32 + seg * 8 + lr) * ALD + nt * 8) * 2;
                ldsm4t(bvh, ad);
                ldsm4t(bvl, ad + 9216 * 2);
                mma16816(oacc[nt], pah[2*kcg],     bvh);
                mma16816(oacc[nt], pal[2*kcg],     bvh);
                mma16816(oacc[nt], pah[2*kcg],     bvl);
                mma16816(oacc[nt], pah[2*kcg+1],   &bvh[2]);
                mma16816(oacc[nt], pal[2*kcg+1],   &bvh[2]);
                mma16816(oacc[nt], pah[2*kcg+1],   &bvl[2]);
            }
        }
    }

    // Epilogue
    float inv0 = 1.0f / l0, inv1 = 1.0f / l1;
    size_t orow = (size_t)(b * GT + t0 + w * 16 + gr) * DIM + hof;
#pragma unroll
    for (int nt = 0; nt < 8; nt++) {
        int col = nt * 8 + qc;
        float v0 = oacc[nt][0] * inv0, v1 = oacc[nt][1] * inv0;
        float v2 = oacc[nt][2] * inv1, v3 = oacc[nt][3] * inv1;
        uint32_t h0 = packbf(v1, v0);
        uint32_t l0p = packbf(v1 - bfhi(h0), v0 - bflo(h0));
        uint32_t h1 = packbf(v3, v2);
        uint32_t l1p = packbf(v3 - bfhi(h1), v2 - bflo(h1));
        *(uint32_t*)&AHo[orow + col] = h0;
        *(uint32_t*)&ALo[orow + col] = l0p;
        *(uint32_t*)&AHo[orow + 8 * DIM + col] = h1;
        *(uint32_t*)&ALo[orow + 8 * DIM + col] = l1p;
    }
}

// ---------------------------------------------------------------------------
// Launch
// ---------------------------------------------------------------------------
extern "C" void kernel_launch(void* const* d_in, const int* in_sizes, int n_in,
                              void* d_out, int out_size)
{
    const float* X_to   = (const float*)d_in[0];
    const float* X_from = (const float*)d_in[1];
    const int*   maskp  = (const int*)  d_in[2];
    const float* Wq = (const float*)d_in[3];
    const float* bq = (const float*)d_in[4];
    const float* Wk = (const float*)d_in[5];
    const float* bk = (const float*)d_in[6];
    const float* Wv = (const float*)d_in[7];
    const float* bv = (const float*)d_in[8];
    const float* Wo = (const float*)d_in[9];
    const float* bo = (const float*)d_in[10];
    float* out = (float*)d_out;

    __nv_bfloat16 *QH,*QL,*KH,*KL,*VH,*VL,*AH,*AL;
    __nv_bfloat16 *XtH,*XtL,*XfH,*XfL;
    __nv_bfloat16 *WqH,*WqL,*WkH,*WkL,*WvH,*WvL,*WoH,*WoL;
    uint32_t* mbits;
    cudaGetSymbolAddress((void**)&QH, g_QH); cudaGetSymbolAddress((void**)&QL, g_QL);
    cudaGetSymbolAddress((void**)&KH, g_KH); cudaGetSymbolAddress((void**)&KL, g_KL);
    cudaGetSymbolAddress((void**)&VH, g_VH); cudaGetSymbolAddress((void**)&VL, g_VL);
    cudaGetSymbolAddress((void**)&AH, g_AH); cudaGetSymbolAddress((void**)&AL, g_AL);
    cudaGetSymbolAddress((void**)&XtH, g_XtH); cudaGetSymbolAddress((void**)&XtL, g_XtL);
    cudaGetSymbolAddress((void**)&XfH, g_XfH); cudaGetSymbolAddress((void**)&XfL, g_XfL);
    cudaGetSymbolAddress((void**)&WqH, g_WqH); cudaGetSymbolAddress((void**)&WqL, g_WqL);
    cudaGetSymbolAddress((void**)&WkH, g_WkH); cudaGetSymbolAddress((void**)&WkL, g_WkL);
    cudaGetSymbolAddress((void**)&WvH, g_WvH); cudaGetSymbolAddress((void**)&WvL, g_WvL);
    cudaGetSymbolAddress((void**)&WoH, g_WoH); cudaGetSymbolAddress((void**)&WoL, g_WoL);
    cudaGetSymbolAddress((void**)&mbits, g_mbits);

    cudaFuncSetAttribute(gemm_mma_bf16x3,
                         cudaFuncAttributeMaxDynamicSharedMemorySize, GEMM_SMEM);
    cudaFuncSetAttribute(attn_mma,
                         cudaFuncAttributeMaxDynamicSharedMemorySize, ATT_SMEM);

    const int nX4 = MTOT * DIM / 4;
    const int nW4 = DIM * DIM / 4;

    split_bf16<<<nX4 / 256, 256>>>((const float4*)X_to,   (uint2*)XtH, (uint2*)XtL, nX4);
    split_bf16<<<nX4 / 256, 256>>>((const float4*)X_from, (uint2*)XfH, (uint2*)XfL, nX4);
    split_bf16<<<nW4 / 256, 256>>>((const float4*)Wq, (uint2*)WqH, (uint2*)WqL, nW4);
    split_bf16<<<nW4 / 256, 256>>>((const float4*)Wk, (uint2*)WkH, (uint2*)WkL, nW4);
    split_bf16<<<nW4 / 256, 256>>>((const float4*)Wv, (uint2*)WvH, (uint2*)WvL, nW4);
    split_bf16<<<nW4 / 256, 256>>>((const float4*)Wo, (uint2*)WoH, (uint2*)WoL, nW4);
    pack_mask<<<(MTOT * GF) / 256, 256>>>(maskp, mbits);

    dim3 gg(DIM / BN, MTOT / BM);   // (8, 32)

    // Projections -> bf16 hi/lo pairs. NOTE reference's swap: K<=Wv/bv, V<=Wk/bk.
    gemm_mma_bf16x3<<<gg, 256, GEMM_SMEM>>>(XtH, XtL, WqH, WqL, bq, nullptr, QH, QL);
    gemm_mma_bf16x3<<<gg, 256, GEMM_SMEM>>>(XfH, XfL, WvH, WvL, bv, nullptr, KH, KL);
    gemm_mma_bf16x3<<<gg, 256, GEMM_SMEM>>>(XfH, XfL, WkH, WkL, bk, nullptr, VH, VL);

    dim3 ag(GT / 128, GH, GB);      // (8, 16, 4)
    attn_mma<<<ag, 256, ATT_SMEM>>>(QH, QL, KH, KL, VH, VL, mbits, AH, AL);

    // Output projection (fp32 out)
    gemm_mma_bf16x3<<<gg, 256, GEMM_SMEM>>>(AH, AL, WoH, WoL, bo, out, nullptr, nullptr);
}

// round 6
// speedup vs baseline: 2.4955x; 1.0094x over previous
#include <cuda_runtime.h>
#include <cuda_bf16.h>
#include <cstdint>
#include <math.h>

// Problem constants
#define GB 4
#define GT 1024
#define GF 1024
#define DIM 1024
#define GH 16
#define HD 64
#define MTOT (GB*GT)   // 4096

// ---------------------------------------------------------------------------
// Scratch (__device__ globals; allocation-free rule)
// ---------------------------------------------------------------------------
__device__ __nv_bfloat16 g_QH[MTOT*DIM], g_QL[MTOT*DIM];
__device__ __nv_bfloat16 g_KH[MTOT*DIM], g_KL[MTOT*DIM];
__device__ __nv_bfloat16 g_VH[MTOT*DIM], g_VL[MTOT*DIM];
__device__ __nv_bfloat16 g_AH[MTOT*DIM], g_AL[MTOT*DIM];
__device__ __nv_bfloat16 g_XtH[MTOT*DIM], g_XtL[MTOT*DIM];
__device__ __nv_bfloat16 g_XfH[MTOT*DIM], g_XfL[MTOT*DIM];
__device__ __nv_bfloat16 g_WqH[DIM*DIM],  g_WqL[DIM*DIM];
__device__ __nv_bfloat16 g_WkH[DIM*DIM],  g_WkL[DIM*DIM];
__device__ __nv_bfloat16 g_WvH[DIM*DIM],  g_WvL[DIM*DIM];
__device__ __nv_bfloat16 g_WoH[DIM*DIM],  g_WoL[DIM*DIM];
__device__ uint32_t g_mbits[MTOT*GF/32];   // bit-packed mask, 512KB

// ---------------------------------------------------------------------------
// Helpers
// ---------------------------------------------------------------------------
__device__ __forceinline__ uint32_t smem_u32(const void* p){
    uint32_t a;
    asm("{ .reg .u64 t; cvta.to.shared.u64 t, %1; cvt.u32.u64 %0, t; }"
        : "=r"(a) : "l"(p));
    return a;
}
__device__ __forceinline__ void ldsm4(uint32_t* r, uint32_t addr){
    asm volatile("ldmatrix.sync.aligned.m8n8.x4.shared.b16 {%0,%1,%2,%3}, [%4];"
        : "=r"(r[0]), "=r"(r[1]), "=r"(r[2]), "=r"(r[3]) : "r"(addr));
}
__device__ __forceinline__ void ldsm4t(uint32_t* r, uint32_t addr){
    asm volatile("ldmatrix.sync.aligned.m8n8.x4.trans.shared.b16 {%0,%1,%2,%3}, [%4];"
        : "=r"(r[0]), "=r"(r[1]), "=r"(r[2]), "=r"(r[3]) : "r"(addr));
}
__device__ __forceinline__ void mma16816(float* d, const uint32_t* a, const uint32_t* b){
    asm volatile("mma.sync.aligned.m16n8k16.row.col.f32.bf16.bf16.f32 "
        "{%0,%1,%2,%3}, {%4,%5,%6,%7}, {%8,%9}, {%0,%1,%2,%3};"
        : "+f"(d[0]), "+f"(d[1]), "+f"(d[2]), "+f"(d[3])
        : "r"(a[0]), "r"(a[1]), "r"(a[2]), "r"(a[3]), "r"(b[0]), "r"(b[1]));
}
__device__ __forceinline__ uint32_t packbf(float hi, float lo){
    uint32_t r;
    asm("cvt.rn.bf16x2.f32 %0, %1, %2;" : "=r"(r) : "f"(hi), "f"(lo));
    return r;
}
__device__ __forceinline__ float bflo(uint32_t r){ return __int_as_float(r << 16); }
__device__ __forceinline__ float bfhi(uint32_t r){ return __int_as_float(r & 0xFFFF0000u); }

// Branch-free exp on FMA/ALU pipes only.
__device__ __forceinline__ float fast_exp(float x){
    float xc = fmaxf(x, -87.0f);
    float r  = fmaf(xc, 1.4426950408889634f, 12582912.0f);
    int   n  = __float_as_int(r) - 0x4B400000;
    float fi = r - 12582912.0f;
    float g  = fmaf(fi, -0.6931471805599453f, xc);
    float p  = 8.3333337e-3f;
    p = fmaf(p, g, 4.1666668e-2f);
    p = fmaf(p, g, 1.6666667e-1f);
    p = fmaf(p, g, 0.5f);
    p = fmaf(p, g, 1.0f);
    p = fmaf(p, g, 1.0f);
    return p * __int_as_float((n << 23) + 0x3F800000);
}

#define CP_ASYNC16(sm, gp) \
    asm volatile("cp.async.cg.shared.global [%0], [%1], 16;" :: "r"(sm), "l"(gp))
#define CP_COMMIT() asm volatile("cp.async.commit_group;")
#define CP_WAIT1()  asm volatile("cp.async.wait_group 1;")

// ---------------------------------------------------------------------------
// Fused prep: all six fp32 -> (bf16 hi, lo) splits in one launch.
// Flat float4 index across [Xt | Xf | Wq | Wk | Wv | Wo].
// ---------------------------------------------------------------------------
#define NX4 (MTOT*DIM/4)   // 1048576
#define NW4 (DIM*DIM/4)    // 262144
#define NPREP (2*NX4 + 4*NW4)

__device__ __forceinline__ void split_one(
    const float4* __restrict__ x, uint2* __restrict__ h, uint2* __restrict__ l, int i)
{
    float4 v = x[i];
    union { __nv_bfloat16 b[4]; uint2 u; } H, L;
    H.b[0] = __float2bfloat16(v.x);
    H.b[1] = __float2bfloat16(v.y);
    H.b[2] = __float2bfloat16(v.z);
    H.b[3] = __float2bfloat16(v.w);
    L.b[0] = __float2bfloat16(v.x - __bfloat162float(H.b[0]));
    L.b[1] = __float2bfloat16(v.y - __bfloat162float(H.b[1]));
    L.b[2] = __float2bfloat16(v.z - __bfloat162float(H.b[2]));
    L.b[3] = __float2bfloat16(v.w - __bfloat162float(H.b[3]));
    h[i] = H.u;
    l[i] = L.u;
}

__global__ __launch_bounds__(256) void prep_split(
    const float4* __restrict__ Xt, const float4* __restrict__ Xf,
    const float4* __restrict__ Wq, const float4* __restrict__ Wk,
    const float4* __restrict__ Wv, const float4* __restrict__ Wo)
{
    int i = blockIdx.x * 256 + threadIdx.x;
    if (i < NX4) {
        split_one(Xt, (uint2*)g_XtH, (uint2*)g_XtL, i);
    } else if (i < 2*NX4) {
        split_one(Xf, (uint2*)g_XfH, (uint2*)g_XfL, i - NX4);
    } else {
        int j = i - 2*NX4;
        if (j < NW4)           split_one(Wq, (uint2*)g_WqH, (uint2*)g_WqL, j);
        else if (j < 2*NW4)    split_one(Wk, (uint2*)g_WkH, (uint2*)g_WkL, j - NW4);
        else if (j < 3*NW4)    split_one(Wv, (uint2*)g_WvH, (uint2*)g_WvL, j - 2*NW4);
        else if (j < 4*NW4)    split_one(Wo, (uint2*)g_WoH, (uint2*)g_WoL, j - 3*NW4);
    }
}

// mask int32 -> bit-packed
__global__ __launch_bounds__(256) void pack_mask(
    const int* __restrict__ m, uint32_t* __restrict__ bits)
{
    int i = blockIdx.x * 256 + threadIdx.x;
    unsigned v = __ballot_sync(0xffffffffu, m[i] != 0);
    if ((threadIdx.x & 31) == 0) bits[i >> 5] = v;
}

// ---------------------------------------------------------------------------
// cp.async double-buffered mma.sync bf16x3 GEMM (unchanged from R4/R5).
// ---------------------------------------------------------------------------
#define BM 128
#define BN 128
#define BK 32
#define LDT 40
#define TSZ (128*LDT)
#define STG (4*TSZ)
#define GEMM_SMEM (2*STG*2)

__device__ __forceinline__ void gemm_issue(
    const __nv_bfloat16* s0, const __nv_bfloat16* s1,
    const __nv_bfloat16* s2, const __nv_bfloat16* s3,
    int kc, uint32_t sstage, int tid)
{
    const __nv_bfloat16* src[4] = { s0, s1, s2, s3 };
#pragma unroll
    for (int t = 0; t < 4; t++) {
#pragma unroll
        for (int j = 0; j < 2; j++) {
            int idx = tid + j * 256;
            int r = idx >> 2, c = (idx & 3) * 8;
            CP_ASYNC16(sstage + (t * TSZ + r * LDT + c) * 2,
                       src[t] + (size_t)r * DIM + kc * BK + c);
        }
    }
}

__global__ __launch_bounds__(256, 2) void gemm_mma_bf16x3(
    const __nv_bfloat16* __restrict__ Ah, const __nv_bfloat16* __restrict__ Al,
    const __nv_bfloat16* __restrict__ Bh, const __nv_bfloat16* __restrict__ Bl,
    const float* __restrict__ bias, float* __restrict__ C,
    __nv_bfloat16* __restrict__ CH, __nv_bfloat16* __restrict__ CL)
{
    extern __shared__ __nv_bfloat16 smb[];
    const int tid = threadIdx.x, wid = tid >> 5, lane = tid & 31;
    const int bm = blockIdx.y * BM, bn = blockIdx.x * BN;
    const int wm = (wid & 1) * 64, wn = (wid >> 1) * 32;

    const __nv_bfloat16* sA0 = Ah + (size_t)bm * DIM;
    const __nv_bfloat16* sA1 = Al + (size_t)bm * DIM;
    const __nv_bfloat16* sB0 = Bh + (size_t)bn * DIM;
    const __nv_bfloat16* sB1 = Bl + (size_t)bn * DIM;

    float acc[4][4][4];
#pragma unroll
    for (int i = 0; i < 4; i++)
#pragma unroll
        for (int j = 0; j < 4; j++)
#pragma unroll
            for (int k = 0; k < 4; k++) acc[i][j][k] = 0.0f;

    const int seg = lane >> 3, lr = lane & 7;
    const int a_row = wm + (seg & 1) * 8 + lr;
    const int a_kof = (seg >> 1) * 8;
    const int b_row = wn + lr;
    const int b_kof = (seg & 1) * 8;

    const uint32_t sb = smem_u32(smb);
    const uint32_t oAh = (a_row * LDT + a_kof) * 2;
    const uint32_t oAl = oAh + TSZ * 2;
    const uint32_t oBh = ((b_row * LDT + b_kof) + 2 * TSZ) * 2;
    const uint32_t oBl = oBh + TSZ * 2;

    gemm_issue(sA0, sA1, sB0, sB1, 0, sb, tid);             CP_COMMIT();
    gemm_issue(sA0, sA1, sB0, sB1, 1, sb + STG * 2, tid);   CP_COMMIT();

    for (int kc = 0; kc < DIM / BK; kc++) {
        CP_WAIT1();
        __syncthreads();
        const uint32_t st = sb + (kc & 1) * (STG * 2);

#pragma unroll
        for (int ks = 0; ks < 2; ks++) {
            const uint32_t ko = ks * 32;
            uint32_t bh[4][2], bl[4][2];
#pragma unroll
            for (int nt = 0; nt < 4; nt++) {
                uint32_t ad = st + nt * (8 * LDT * 2) + ko;
                asm volatile("ldmatrix.sync.aligned.m8n8.x2.shared.b16 {%0,%1}, [%2];"
                    : "=r"(bh[nt][0]), "=r"(bh[nt][1]) : "r"(ad + oBh));
                asm volatile("ldmatrix.sync.aligned.m8n8.x2.shared.b16 {%0,%1}, [%2];"
                    : "=r"(bl[nt][0]), "=r"(bl[nt][1]) : "r"(ad + oBl));
            }
#pragma unroll
            for (int mt = 0; mt < 4; mt++) {
                uint32_t ah[4], al[4];
                uint32_t ad = st + mt * (16 * LDT * 2) + ko;
                ldsm4(ah, ad + oAh);
                ldsm4(al, ad + oAl);
#pragma unroll
                for (int nt = 0; nt < 4; nt++) {
                    mma16816(acc[mt][nt], ah, bh[nt]);
                    mma16816(acc[mt][nt], ah, bl[nt]);
                    mma16816(acc[mt][nt], al, bh[nt]);
                }
            }
        }
        __syncthreads();
        if (kc + 2 < DIM / BK)
            gemm_issue(sA0, sA1, sB0, sB1, kc + 2, sb + ((kc + 2) & 1) * (STG * 2), tid);
        CP_COMMIT();
    }

    const int gr = lane >> 2, gc = (lane & 3) * 2;
#pragma unroll
    for (int mt = 0; mt < 4; mt++) {
#pragma unroll
        for (int nt = 0; nt < 4; nt++) {
            int col  = bn + wn + nt * 8 + gc;
            float b0 = bias[col], b1 = bias[col + 1];
            size_t r0 = (size_t)(bm + wm + mt * 16 + gr) * DIM + col;
            size_t r1 = r0 + 8 * DIM;
            float v0 = acc[mt][nt][0] + b0, v1 = acc[mt][nt][1] + b1;
            float v2 = acc[mt][nt][2] + b0, v3 = acc[mt][nt][3] + b1;
            if (CH) {
                uint32_t h0 = packbf(v1, v0);
                uint32_t l0 = packbf(v1 - bfhi(h0), v0 - bflo(h0));
                uint32_t h1 = packbf(v3, v2);
                uint32_t l1 = packbf(v3 - bfhi(h1), v2 - bflo(h1));
                *(uint32_t*)&CH[r0] = h0; *(uint32_t*)&CL[r0] = l0;
                *(uint32_t*)&CH[r1] = h1; *(uint32_t*)&CL[r1] = l1;
            } else {
                float2 w0 = { v0, v1 }, w1 = { v2, v3 };
                *(float2*)&C[r0] = w0;
                *(float2*)&C[r1] = w1;
            }
        }
    }
}

// ---------------------------------------------------------------------------
// Tensor-core flash attention, FT=64 (register-pressure fix).
// 128 t-rows per CTA, 8 warps; 16 f-tiles of 64 rows, 2-stage cp.async KV.
// ---------------------------------------------------------------------------
#define ALD 72
#define SQH 0
#define SQL 9216
#define SKV0 18432
#define KVARR 4608            // bf16 units per 64x72 array
#define KVSTG (4*KVARR)       // 18432 per stage
#define ATT_SMEM ((SKV0 + 2*KVSTG)*2)   // 110592 bytes

__device__ __forceinline__ void kv_issue(
    const __nv_bfloat16* KH, const __nv_bfloat16* KL,
    const __nv_bfloat16* VH, const __nv_bfloat16* VL,
    size_t gfrow, int hof, uint32_t stbase, int tid)
{
#pragma unroll
    for (int j = 0; j < 2; j++) {
        int idx = tid + j * 256;       // 0..511
        int r = idx >> 3, c = (idx & 7) * 8;
        size_t g = (gfrow + r) * DIM + hof + c;
        uint32_t so = stbase + (r * ALD + c) * 2;
        CP_ASYNC16(so,                KH + g);
        CP_ASYNC16(so + KVARR * 2,    KL + g);
        CP_ASYNC16(so + 2*KVARR * 2,  VH + g);
        CP_ASYNC16(so + 3*KVARR * 2,  VL + g);
    }
}

__global__ __launch_bounds__(256, 1) void attn_mma(
    const __nv_bfloat16* __restrict__ QH, const __nv_bfloat16* __restrict__ QL,
    const __nv_bfloat16* __restrict__ KH, const __nv_bfloat16* __restrict__ KL,
    const __nv_bfloat16* __restrict__ VH, const __nv_bfloat16* __restrict__ VL,
    const uint32_t* __restrict__ mbits,
    __nv_bfloat16* __restrict__ AHo, __nv_bfloat16* __restrict__ ALo)
{
    extern __shared__ __nv_bfloat16 sm[];
    const int tid = threadIdx.x, w = tid >> 5, lane = tid & 31;
    const int t0 = blockIdx.x * 128, h = blockIdx.y, b = blockIdx.z;
    const int lr = lane & 7, seg = lane >> 3;
    const int gr = lane >> 2, qc = (lane & 3) * 2;
    const uint32_t sb = smem_u32(sm);
    const int hof = h * HD;
    const size_t gfbase = (size_t)(b * GF);

    // prefetch KV stage 0
    kv_issue(KH, KL, VH, VL, gfbase, hof, sb + SKV0 * 2, tid);
    CP_COMMIT();

    // Load Q tile (hi/lo)
    {
        const size_t grow = (size_t)(b * GT + t0);
#pragma unroll
        for (int j = 0; j < 4; j++) {
            int idx = tid + j * 256;
            int r = idx >> 3, c = (idx & 7) * 8;
            size_t g = (grow + r) * DIM + hof + c;
            *(uint4*)&sm[SQH + r * ALD + c] = *(const uint4*)&QH[g];
            *(uint4*)&sm[SQL + r * ALD + c] = *(const uint4*)&QL[g];
        }
    }
    __syncthreads();

    uint32_t qh[4][4], ql[4][4];
#pragma unroll
    for (int kc = 0; kc < 4; kc++) {
        uint32_t ad = sb + ((w * 16 + (seg & 1) * 8 + lr) * ALD + kc * 16 + (seg >> 1) * 8) * 2;
        ldsm4(qh[kc], ad + SQH * 2);
        ldsm4(ql[kc], ad + SQL * 2);
    }

    float oacc[8][4];
#pragma unroll
    for (int i = 0; i < 8; i++)
#pragma unroll
        for (int j = 0; j < 4; j++) oacc[i][j] = 0.0f;
    float m0 = -1e30f, m1 = -1e30f, l0 = 0.0f, l1 = 0.0f;

    const int mrow0 = b * GT + t0 + w * 16 + gr;
    const uint32_t* mrp0 = mbits + (size_t)mrow0 * (GF / 32);
    const uint32_t* mrp1 = mrp0 + 8 * (GF / 32);

    for (int ftile = 0; ftile < 16; ftile++) {
        __syncthreads();
        if (ftile + 1 < 16)
            kv_issue(KH, KL, VH, VL, gfbase + (ftile + 1) * 64, hof,
                     sb + (SKV0 + ((ftile + 1) & 1) * KVSTG) * 2, tid);
        CP_COMMIT();
        CP_WAIT1();
        __syncthreads();

        const uint32_t stg = SKV0 + (ftile & 1) * KVSTG;

        // mask bits for this 64-col tile
        uint2 mw0 = *(const uint2*)(mrp0 + ftile * 2);
        uint2 mw1 = *(const uint2*)(mrp1 + ftile * 2);
        uint32_t wA[2] = { mw0.x, mw0.y };
        uint32_t wB[2] = { mw1.x, mw1.y };

        // S = Q K^T (bf16x3), 8 nt
        float sacc[8][4];
#pragma unroll
        for (int nt = 0; nt < 8; nt++) {
#pragma unroll
            for (int j = 0; j < 4; j++) sacc[nt][j] = 0.0f;
        }
#pragma unroll
        for (int nt = 0; nt < 8; nt++) {
            uint32_t bh[8], bl[8];
#pragma unroll
            for (int kcg = 0; kcg < 2; kcg++) {
                uint32_t ad = sb + (stg + (nt * 8 + lr) * ALD + kcg * 32 + seg * 8) * 2;
                ldsm4(&bh[kcg * 4], ad);
                ldsm4(&bl[kcg * 4], ad + KVARR * 2);
            }
#pragma unroll
            for (int kc = 0; kc < 4; kc++) {
                mma16816(sacc[nt], qh[kc], &bh[kc * 2]);
                mma16816(sacc[nt], qh[kc], &bl[kc * 2]);
                mma16816(sacc[nt], ql[kc], &bh[kc * 2]);
            }
        }

        // mask + scale + row max
        float rm0 = -1e30f, rm1 = -1e30f;
#pragma unroll
        for (int nt = 0; nt < 8; nt++) {
            uint32_t sh = (nt & 3) * 8 + qc;
            uint32_t bA = wA[nt >> 2] >> sh;
            uint32_t bB = wB[nt >> 2] >> sh;
            float s0 = (bA & 1u) ? sacc[nt][0] * 0.125f : -10000.0f;
            float s1 = (bA & 2u) ? sacc[nt][1] * 0.125f : -10000.0f;
            float s2 = (bB & 1u) ? sacc[nt][2] * 0.125f : -10000.0f;
            float s3 = (bB & 2u) ? sacc[nt][3] * 0.125f : -10000.0f;
            sacc[nt][0] = s0; sacc[nt][1] = s1; sacc[nt][2] = s2; sacc[nt][3] = s3;
            rm0 = fmaxf(rm0, fmaxf(s0, s1));
            rm1 = fmaxf(rm1, fmaxf(s2, s3));
        }
        rm0 = fmaxf(rm0, __shfl_xor_sync(0xffffffffu, rm0, 1));
        rm0 = fmaxf(rm0, __shfl_xor_sync(0xffffffffu, rm0, 2));
        rm1 = fmaxf(rm1, __shfl_xor_sync(0xffffffffu, rm1, 1));
        rm1 = fmaxf(rm1, __shfl_xor_sync(0xffffffffu, rm1, 2));
        float mn0 = fmaxf(m0, rm0), mn1 = fmaxf(m1, rm1);
        float c0 = fast_exp(m0 - mn0), c1 = fast_exp(m1 - mn1);
        m0 = mn0; m1 = mn1;

        // P = exp(s-m), pack A-frags hi/lo (4 k16-steps), row sums
        uint32_t pah[4][4], pal[4][4];
        float rs0 = 0.0f, rs1 = 0.0f;
#pragma unroll
        for (int kc = 0; kc < 4; kc++) {
            float p0 = fast_exp(sacc[2*kc][0] - m0);
            float p1 = fast_exp(sacc[2*kc][1] - m0);
            float p2 = fast_exp(sacc[2*kc][2] - m1);
            float p3 = fast_exp(sacc[2*kc][3] - m1);
            float p4 = fast_exp(sacc[2*kc+1][0] - m0);
            float p5 = fast_exp(sacc[2*kc+1][1] - m0);
            float p6 = fast_exp(sacc[2*kc+1][2] - m1);
            float p7 = fast_exp(sacc[2*kc+1][3] - m1);
            rs0 += (p0 + p1) + (p4 + p5);
            rs1 += (p2 + p3) + (p6 + p7);
            uint32_t h0 = packbf(p1, p0), h1 = packbf(p3, p2);
            uint32_t h2 = packbf(p5, p4), h3 = packbf(p7, p6);
            pah[kc][0] = h0; pah[kc][1] = h1; pah[kc][2] = h2; pah[kc][3] = h3;
            pal[kc][0] = packbf(p1 - bfhi(h0), p0 - bflo(h0));
            pal[kc][1] = packbf(p3 - bfhi(h1), p2 - bflo(h1));
            pal[kc][2] = packbf(p5 - bfhi(h2), p4 - bflo(h2));
            pal[kc][3] = packbf(p7 - bfhi(h3), p6 - bflo(h3));
        }
        rs0 += __shfl_xor_sync(0xffffffffu, rs0, 1);
        rs0 += __shfl_xor_sync(0xffffffffu, rs0, 2);
        rs1 += __shfl_xor_sync(0xffffffffu, rs1, 1);
        rs1 += __shfl_xor_sync(0xffffffffu, rs1, 2);
        l0 = l0 * c0 + rs0;
        l1 = l1 * c1 + rs1;

#pragma unroll
        for (int nt = 0; nt < 8; nt++) {
            oacc[nt][0] *= c0; oacc[nt][1] *= c0;
            oacc[nt][2] *= c1; oacc[nt][3] *= c1;
        }

        // O += P V (bf16x3), k=64 in 2 kcg groups
#pragma unroll
        for (int kcg = 0; kcg < 2; kcg++) {
#pragma unroll
            for (int nt = 0; nt < 8; nt++) {
                uint32_t bvh[4], bvl[4];
                uint32_t ad = sb + (stg + 2*KVARR + (kcg * 32 + seg * 8 + lr) * ALD + nt * 8) * 2;
                ldsm4t(bvh, ad);
                ldsm4t(bvl, ad + KVARR * 2);
                mma16816(oacc[nt], pah[2*kcg],     bvh);
                mma16816(oacc[nt], pal[2*kcg],     bvh);
                mma16816(oacc[nt], pah[2*kcg],     bvl);
                mma16816(oacc[nt], pah[2*kcg+1],   &bvh[2]);
                mma16816(oacc[nt], pal[2*kcg+1],   &bvh[2]);
                mma16816(oacc[nt], pah[2*kcg+1],   &bvl[2]);
            }
        }
    }

    // Epilogue
    float inv0 = 1.0f / l0, inv1 = 1.0f / l1;
    size_t orow = (size_t)(b * GT + t0 + w * 16 + gr) * DIM + hof;
#pragma unroll
    for (int nt = 0; nt < 8; nt++) {
        int col = nt * 8 + qc;
        float v0 = oacc[nt][0] * inv0, v1 = oacc[nt][1] * inv0;
        float v2 = oacc[nt][2] * inv1, v3 = oacc[nt][3] * inv1;
        uint32_t h0 = packbf(v1, v0);
        uint32_t l0p = packbf(v1 - bfhi(h0), v0 - bflo(h0));
        uint32_t h1 = packbf(v3, v2);
        uint32_t l1p = packbf(v3 - bfhi(h1), v2 - bflo(h1));
        *(uint32_t*)&AHo[orow + col] = h0;
        *(uint32_t*)&ALo[orow + col] = l0p;
        *(uint32_t*)&AHo[orow + 8 * DIM + col] = h1;
        *(uint32_t*)&ALo[orow + 8 * DIM + col] = l1p;
    }
}

// ---------------------------------------------------------------------------
// Launch
// ---------------------------------------------------------------------------
extern "C" void kernel_launch(void* const* d_in, const int* in_sizes, int n_in,
                              void* d_out, int out_size)
{
    const float* X_to   = (const float*)d_in[0];
    const float* X_from = (const float*)d_in[1];
    const int*   maskp  = (const int*)  d_in[2];
    const float* Wq = (const float*)d_in[3];
    const float* bq = (const float*)d_in[4];
    const float* Wk = (const float*)d_in[5];
    const float* bk = (const float*)d_in[6];
    const float* Wv = (const float*)d_in[7];
    const float* bv = (const float*)d_in[8];
    const float* Wo = (const float*)d_in[9];
    const float* bo = (const float*)d_in[10];
    float* out = (float*)d_out;

    __nv_bfloat16 *QH,*QL,*KH,*KL,*VH,*VL,*AH,*AL;
    __nv_bfloat16 *XtH,*XtL,*XfH,*XfL;
    __nv_bfloat16 *WqH,*WqL,*WkH,*WkL,*WvH,*WvL,*WoH,*WoL;
    uint32_t* mbits;
    cudaGetSymbolAddress((void**)&QH, g_QH); cudaGetSymbolAddress((void**)&QL, g_QL);
    cudaGetSymbolAddress((void**)&KH, g_KH); cudaGetSymbolAddress((void**)&KL, g_KL);
    cudaGetSymbolAddress((void**)&VH, g_VH); cudaGetSymbolAddress((void**)&VL, g_VL);
    cudaGetSymbolAddress((void**)&AH, g_AH); cudaGetSymbolAddress((void**)&AL, g_AL);
    cudaGetSymbolAddress((void**)&XtH, g_XtH); cudaGetSymbolAddress((void**)&XtL, g_XtL);
    cudaGetSymbolAddress((void**)&XfH, g_XfH); cudaGetSymbolAddress((void**)&XfL, g_XfL);
    cudaGetSymbolAddress((void**)&WqH, g_WqH); cudaGetSymbolAddress((void**)&WqL, g_WqL);
    cudaGetSymbolAddress((void**)&WkH, g_WkH); cudaGetSymbolAddress((void**)&WkL, g_WkL);
    cudaGetSymbolAddress((void**)&WvH, g_WvH); cudaGetSymbolAddress((void**)&WvL, g_WvL);
    cudaGetSymbolAddress((void**)&WoH, g_WoH); cudaGetSymbolAddress((void**)&WoL, g_WoL);
    cudaGetSymbolAddress((void**)&mbits, g_mbits);

    cudaFuncSetAttribute(gemm_mma_bf16x3,
                         cudaFuncAttributeMaxDynamicSharedMemorySize, GEMM_SMEM);
    cudaFuncSetAttribute(attn_mma,
                         cudaFuncAttributeMaxDynamicSharedMemorySize, ATT_SMEM);

    // Fused splits + mask pack
    prep_split<<<NPREP / 256, 256>>>((const float4*)X_to, (const float4*)X_from,
                                     (const float4*)Wq, (const float4*)Wk,
                                     (const float4*)Wv, (const float4*)Wo);
    pack_mask<<<(MTOT * GF) / 256, 256>>>(maskp, mbits);

    dim3 gg(DIM / BN, MTOT / BM);   // (8, 32)

    // Projections -> bf16 hi/lo pairs. NOTE reference's swap: K<=Wv/bv, V<=Wk/bk.
    gemm_mma_bf16x3<<<gg, 256, GEMM_SMEM>>>(XtH, XtL, WqH, WqL, bq, nullptr, QH, QL);
    gemm_mma_bf16x3<<<gg, 256, GEMM_SMEM>>>(XfH, XfL, WvH, WvL, bv, nullptr, KH, KL);
    gemm_mma_bf16x3<<<gg, 256, GEMM_SMEM>>>(XfH, XfL, WkH, WkL, bk, nullptr, VH, VL);

    dim3 ag(GT / 128, GH, GB);      // (8, 16, 4)
    attn_mma<<<ag, 256, ATT_SMEM>>>(QH, QL, KH, KL, VH, VL, mbits, AH, AL);

    // Output projection (fp32 out)
    gemm_mma_bf16x3<<<gg, 256, GEMM_SMEM>>>(AH, AL, WoH, WoL, bo, out, nullptr, nullptr);
}

// round 8
// speedup vs baseline: 2.7395x; 1.0978x over previous
#include <cuda_runtime.h>
#include <cuda_bf16.h>
#include <cstdint>
#include <math.h>

// Problem constants
#define GB 4
#define GT 1024
#define GF 1024
#define DIM 1024
#define GH 16
#define HD 64
#define MTOT (GB*GT)   // 4096

// ---------------------------------------------------------------------------
// Scratch (__device__ globals; allocation-free rule)
// ---------------------------------------------------------------------------
__device__ __nv_bfloat16 g_QH[MTOT*DIM], g_QL[MTOT*DIM];
__device__ __nv_bfloat16 g_KH[MTOT*DIM], g_KL[MTOT*DIM];
__device__ __nv_bfloat16 g_VH[MTOT*DIM], g_VL[MTOT*DIM];
__device__ __nv_bfloat16 g_AH[MTOT*DIM], g_AL[MTOT*DIM];
__device__ __nv_bfloat16 g_XtH[MTOT*DIM], g_XtL[MTOT*DIM];
__device__ __nv_bfloat16 g_XfH[MTOT*DIM], g_XfL[MTOT*DIM];
__device__ __nv_bfloat16 g_WqH[DIM*DIM],  g_WqL[DIM*DIM];
__device__ __nv_bfloat16 g_WkH[DIM*DIM],  g_WkL[DIM*DIM];
__device__ __nv_bfloat16 g_WvH[DIM*DIM],  g_WvL[DIM*DIM];
__device__ __nv_bfloat16 g_WoH[DIM*DIM],  g_WoL[DIM*DIM];
__device__ uint32_t g_mbits[MTOT*GF/32];

// ---------------------------------------------------------------------------
// Helpers
// ---------------------------------------------------------------------------
__device__ __forceinline__ uint32_t smem_u32(const void* p){
    uint32_t a;
    asm("{ .reg .u64 t; cvta.to.shared.u64 t, %1; cvt.u32.u64 %0, t; }"
        : "=r"(a) : "l"(p));
    return a;
}
__device__ __forceinline__ void ldsm4(uint32_t* r, uint32_t addr){
    asm volatile("ldmatrix.sync.aligned.m8n8.x4.shared.b16 {%0,%1,%2,%3}, [%4];"
        : "=r"(r[0]), "=r"(r[1]), "=r"(r[2]), "=r"(r[3]) : "r"(addr));
}
__device__ __forceinline__ void ldsm2(uint32_t* r, uint32_t addr){
    asm volatile("ldmatrix.sync.aligned.m8n8.x2.shared.b16 {%0,%1}, [%2];"
        : "=r"(r[0]), "=r"(r[1]) : "r"(addr));
}
__device__ __forceinline__ void ldsm4t(uint32_t* r, uint32_t addr){
    asm volatile("ldmatrix.sync.aligned.m8n8.x4.trans.shared.b16 {%0,%1,%2,%3}, [%4];"
        : "=r"(r[0]), "=r"(r[1]), "=r"(r[2]), "=r"(r[3]) : "r"(addr));
}
__device__ __forceinline__ void mma16816(float* d, const uint32_t* a, const uint32_t* b){
    asm volatile("mma.sync.aligned.m16n8k16.row.col.f32.bf16.bf16.f32 "
        "{%0,%1,%2,%3}, {%4,%5,%6,%7}, {%8,%9}, {%0,%1,%2,%3};"
        : "+f"(d[0]), "+f"(d[1]), "+f"(d[2]), "+f"(d[3])
        : "r"(a[0]), "r"(a[1]), "r"(a[2]), "r"(a[3]), "r"(b[0]), "r"(b[1]));
}
__device__ __forceinline__ uint32_t packbf(float hi, float lo){
    uint32_t r;
    asm("cvt.rn.bf16x2.f32 %0, %1, %2;" : "=r"(r) : "f"(hi), "f"(lo));
    return r;
}
__device__ __forceinline__ float bflo(uint32_t r){ return __int_as_float(r << 16); }
__device__ __forceinline__ float bfhi(uint32_t r){ return __int_as_float(r & 0xFFFF0000u); }

// Branch-free exp on FMA/ALU pipes only.
__device__ __forceinline__ float fast_exp(float x){
    float xc = fmaxf(x, -87.0f);
    float r  = fmaf(xc, 1.4426950408889634f, 12582912.0f);
    int   n  = __float_as_int(r) - 0x4B400000;
    float fi = r - 12582912.0f;
    float g  = fmaf(fi, -0.6931471805599453f, xc);
    float p  = 8.3333337e-3f;
    p = fmaf(p, g, 4.1666668e-2f);
    p = fmaf(p, g, 1.6666667e-1f);
    p = fmaf(p, g, 0.5f);
    p = fmaf(p, g, 1.0f);
    p = fmaf(p, g, 1.0f);
    return p * __int_as_float((n << 23) + 0x3F800000);
}

#define CP_ASYNC16(sm, gp) \
    asm volatile("cp.async.cg.shared.global [%0], [%1], 16;" :: "r"(sm), "l"(gp))
#define CP_COMMIT() asm volatile("cp.async.commit_group;")
#define CP_WAIT1()  asm volatile("cp.async.wait_group 1;")

// ---------------------------------------------------------------------------
// Fused prep: all six fp32 -> (bf16 hi, lo) splits in one launch.
// ---------------------------------------------------------------------------
#define NX4 (MTOT*DIM/4)
#define NW4 (DIM*DIM/4)
#define NPREP (2*NX4 + 4*NW4)

__device__ __forceinline__ void split_one(
    const float4* __restrict__ x, uint2* __restrict__ h, uint2* __restrict__ l, int i)
{
    float4 v = x[i];
    union { __nv_bfloat16 b[4]; uint2 u; } H, L;
    H.b[0] = __float2bfloat16(v.x);
    H.b[1] = __float2bfloat16(v.y);
    H.b[2] = __float2bfloat16(v.z);
    H.b[3] = __float2bfloat16(v.w);
    L.b[0] = __float2bfloat16(v.x - __bfloat162float(H.b[0]));
    L.b[1] = __float2bfloat16(v.y - __bfloat162float(H.b[1]));
    L.b[2] = __float2bfloat16(v.z - __bfloat162float(H.b[2]));
    L.b[3] = __float2bfloat16(v.w - __bfloat162float(H.b[3]));
    h[i] = H.u;
    l[i] = L.u;
}

__global__ __launch_bounds__(256) void prep_split(
    const float4* __restrict__ Xt, const float4* __restrict__ Xf,
    const float4* __restrict__ Wq, const float4* __restrict__ Wk,
    const float4* __restrict__ Wv, const float4* __restrict__ Wo)
{
    int i = blockIdx.x * 256 + threadIdx.x;
    if (i < NX4) {
        split_one(Xt, (uint2*)g_XtH, (uint2*)g_XtL, i);
    } else if (i < 2*NX4) {
        split_one(Xf, (uint2*)g_XfH, (uint2*)g_XfL, i - NX4);
    } else {
        int j = i - 2*NX4;
        if (j < NW4)           split_one(Wq, (uint2*)g_WqH, (uint2*)g_WqL, j);
        else if (j < 2*NW4)    split_one(Wk, (uint2*)g_WkH, (uint2*)g_WkL, j - NW4);
        else if (j < 3*NW4)    split_one(Wv, (uint2*)g_WvH, (uint2*)g_WvL, j - 2*NW4);
        else if (j < 4*NW4)    split_one(Wo, (uint2*)g_WoH, (uint2*)g_WoL, j - 3*NW4);
    }
}

__global__ __launch_bounds__(256) void pack_mask(
    const int* __restrict__ m, uint32_t* __restrict__ bits)
{
    int i = blockIdx.x * 256 + threadIdx.x;
    unsigned v = __ballot_sync(0xffffffffu, m[i] != 0);
    if ((threadIdx.x & 31) == 0) bits[i >> 5] = v;
}

// ---------------------------------------------------------------------------
// 3-stage single-sync cp.async mma.sync bf16x3 GEMM.
// LDT=32 (64B rows) with XOR swizzle: chunk' = chunk ^ ((row>>1)&3).
// 16B-aligned ldmatrix addrs + conflict-free banks.
// ---------------------------------------------------------------------------
#define BM 128
#define BN 128
#define BK 32
#define TSZB 8192               // bytes per 128x32 bf16 tile
#define SSTGB (4*TSZB)          // 32768 bytes per stage
#define GEMM_SMEM (3*SSTGB)     // 98304 bytes

__device__ __forceinline__ void gemm_issue(
    const __nv_bfloat16* s0, const __nv_bfloat16* s1,
    const __nv_bfloat16* s2, const __nv_bfloat16* s3,
    int kc, uint32_t sstage, int tid)
{
    const __nv_bfloat16* src[4] = { s0, s1, s2, s3 };
#pragma unroll
    for (int t = 0; t < 4; t++) {
#pragma unroll
        for (int j = 0; j < 2; j++) {
            int idx = tid + j * 256;          // 0..511
            int r = idx >> 2, c = idx & 3;    // row, 16B chunk
            int cs = c ^ ((r >> 1) & 3);      // swizzled chunk
            CP_ASYNC16(sstage + t * TSZB + r * 64 + cs * 16,
                       src[t] + (size_t)r * DIM + kc * BK + c * 8);
        }
    }
}

__global__ __launch_bounds__(256, 2) void gemm_mma_bf16x3(
    const __nv_bfloat16* __restrict__ Ah, const __nv_bfloat16* __restrict__ Al,
    const __nv_bfloat16* __restrict__ Bh, const __nv_bfloat16* __restrict__ Bl,
    const float* __restrict__ bias, float* __restrict__ C,
    __nv_bfloat16* __restrict__ CH, __nv_bfloat16* __restrict__ CL)
{
    extern __shared__ __nv_bfloat16 smb[];
    const int tid = threadIdx.x, wid = tid >> 5, lane = tid & 31;
    const int bm = blockIdx.y * BM, bn = blockIdx.x * BN;
    const int wm = (wid & 1) * 64, wn = (wid >> 1) * 32;

    const __nv_bfloat16* sA0 = Ah + (size_t)bm * DIM;
    const __nv_bfloat16* sA1 = Al + (size_t)bm * DIM;
    const __nv_bfloat16* sB0 = Bh + (size_t)bn * DIM;
    const __nv_bfloat16* sB1 = Bl + (size_t)bn * DIM;

    float acc[4][4][4];
#pragma unroll
    for (int i = 0; i < 4; i++)
#pragma unroll
        for (int j = 0; j < 4; j++)
#pragma unroll
            for (int k = 0; k < 4; k++) acc[i][j][k] = 0.0f;

    const int seg = lane >> 3, lr = lane & 7;
    const int swz = (lr >> 1) & 3;                       // per-thread constant
    const int a_rowb = (wm + (seg & 1) * 8 + lr) * 64;   // byte row offset
    const int b_rowb = (wn + lr) * 64;
    // swizzled chunk byte offsets per k16-step
    const int cA0 = (((seg >> 1)    ) ^ swz) << 4;
    const int cA1 = (((seg >> 1) + 2) ^ swz) << 4;
    const int cB0 = (((seg & 1)     ) ^ swz) << 4;
    const int cB1 = (((seg & 1) + 2) ^ swz) << 4;

    const uint32_t sb = smem_u32(smb);

    // Multistage prologue
    gemm_issue(sA0, sA1, sB0, sB1, 0, sb, tid);          CP_COMMIT();
    gemm_issue(sA0, sA1, sB0, sB1, 1, sb + SSTGB, tid);  CP_COMMIT();
    CP_WAIT1();
    __syncthreads();

    for (int kc = 0; kc < DIM / BK; kc++) {
        if (kc + 2 < DIM / BK)
            gemm_issue(sA0, sA1, sB0, sB1, kc + 2,
                       sb + ((kc + 2) % 3) * SSTGB, tid);
        CP_COMMIT();

        const uint32_t st = sb + (kc % 3) * SSTGB;
#pragma unroll
        for (int ks = 0; ks < 2; ks++) {
            const int cA = ks ? cA1 : cA0;
            const int cB = ks ? cB1 : cB0;
            uint32_t bh[4][2], bl[4][2];
#pragma unroll
            for (int nt = 0; nt < 4; nt++) {
                uint32_t ad = st + 2 * TSZB + b_rowb + nt * (8 * 64) + cB;
                ldsm2(bh[nt], ad);
                ldsm2(bl[nt], ad + TSZB);
            }
#pragma unroll
            for (int mt = 0; mt < 4; mt++) {
                uint32_t ah[4], al[4];
                uint32_t ad = st + a_rowb + mt * (16 * 64) + cA;
                ldsm4(ah, ad);
                ldsm4(al, ad + TSZB);
#pragma unroll
                for (int nt = 0; nt < 4; nt++) {
                    mma16816(acc[mt][nt], ah, bh[nt]);
                    mma16816(acc[mt][nt], ah, bl[nt]);
                    mma16816(acc[mt][nt], al, bh[nt]);
                }
            }
        }

        CP_WAIT1();
        __syncthreads();
    }

    const int gr = lane >> 2, gc = (lane & 3) * 2;
#pragma unroll
    for (int mt = 0; mt < 4; mt++) {
#pragma unroll
        for (int nt = 0; nt < 4; nt++) {
            int col  = bn + wn + nt * 8 + gc;
            float b0 = bias[col], b1 = bias[col + 1];
            size_t r0 = (size_t)(bm + wm + mt * 16 + gr) * DIM + col;
            size_t r1 = r0 + 8 * DIM;
            float v0 = acc[mt][nt][0] + b0, v1 = acc[mt][nt][1] + b1;
            float v2 = acc[mt][nt][2] + b0, v3 = acc[mt][nt][3] + b1;
            if (CH) {
                uint32_t h0 = packbf(v1, v0);
                uint32_t l0 = packbf(v1 - bfhi(h0), v0 - bflo(h0));
                uint32_t h1 = packbf(v3, v2);
                uint32_t l1 = packbf(v3 - bfhi(h1), v2 - bflo(h1));
                *(uint32_t*)&CH[r0] = h0; *(uint32_t*)&CL[r0] = l0;
                *(uint32_t*)&CH[r1] = h1; *(uint32_t*)&CL[r1] = l1;
            } else {
                float2 w0 = { v0, v1 }, w1 = { v2, v3 };
                *(float2*)&C[r0] = w0;
                *(float2*)&C[r1] = w1;
            }
        }
    }
}

// ---------------------------------------------------------------------------
// Tensor-core flash attention, FT=64, 3-stage single-sync KV pipeline.
// (ALD=72 -> 144B rows: 16B-aligned, conflict-free.)
// ---------------------------------------------------------------------------
#define ALD 72
#define SQH 0
#define SQL 9216
#define SKV0 18432
#define KVARR 4608
#define KVSTG (4*KVARR)
#define ATT_SMEM ((SKV0 + 3*KVSTG)*2)   // 147456 bytes

__device__ __forceinline__ void kv_issue(
    const __nv_bfloat16* KH, const __nv_bfloat16* KL,
    const __nv_bfloat16* VH, const __nv_bfloat16* VL,
    size_t gfrow, int hof, uint32_t stbase, int tid)
{
#pragma unroll
    for (int j = 0; j < 2; j++) {
        int idx = tid + j * 256;
        int r = idx >> 3, c = (idx & 7) * 8;
        size_t g = (gfrow + r) * DIM + hof + c;
        uint32_t so = stbase + (r * ALD + c) * 2;
        CP_ASYNC16(so,                KH + g);
        CP_ASYNC16(so + KVARR * 2,    KL + g);
        CP_ASYNC16(so + 2*KVARR * 2,  VH + g);
        CP_ASYNC16(so + 3*KVARR * 2,  VL + g);
    }
}

__global__ __launch_bounds__(256, 1) void attn_mma(
    const __nv_bfloat16* __restrict__ QH, const __nv_bfloat16* __restrict__ QL,
    const __nv_bfloat16* __restrict__ KH, const __nv_bfloat16* __restrict__ KL,
    const __nv_bfloat16* __restrict__ VH, const __nv_bfloat16* __restrict__ VL,
    const uint32_t* __restrict__ mbits,
    __nv_bfloat16* __restrict__ AHo, __nv_bfloat16* __restrict__ ALo)
{
    extern __shared__ __nv_bfloat16 sm[];
    const int tid = threadIdx.x, w = tid >> 5, lane = tid & 31;
    const int t0 = blockIdx.x * 128, h = blockIdx.y, b = blockIdx.z;
    const int lr = lane & 7, seg = lane >> 3;
    const int gr = lane >> 2, qc = (lane & 3) * 2;
    const uint32_t sb = smem_u32(sm);
    const int hof = h * HD;
    const size_t gfbase = (size_t)(b * GF);

    kv_issue(KH, KL, VH, VL, gfbase,      hof, sb + SKV0 * 2, tid);           CP_COMMIT();
    kv_issue(KH, KL, VH, VL, gfbase + 64, hof, sb + (SKV0 + KVSTG) * 2, tid); CP_COMMIT();

    // Load Q tile (hi/lo)
    {
        const size_t grow = (size_t)(b * GT + t0);
#pragma unroll
        for (int j = 0; j < 4; j++) {
            int idx = tid + j * 256;
            int r = idx >> 3, c = (idx & 7) * 8;
            size_t g = (grow + r) * DIM + hof + c;
            *(uint4*)&sm[SQH + r * ALD + c] = *(const uint4*)&QH[g];
            *(uint4*)&sm[SQL + r * ALD + c] = *(const uint4*)&QL[g];
        }
    }
    CP_WAIT1();
    __syncthreads();

    uint32_t qh[4][4], ql[4][4];
#pragma unroll
    for (int kc = 0; kc < 4; kc++) {
        uint32_t ad = sb + ((w * 16 + (seg & 1) * 8 + lr) * ALD + kc * 16 + (seg >> 1) * 8) * 2;
        ldsm4(qh[kc], ad + SQH * 2);
        ldsm4(ql[kc], ad + SQL * 2);
    }

    float oacc[8][4];
#pragma unroll
    for (int i = 0; i < 8; i++)
#pragma unroll
        for (int j = 0; j < 4; j++) oacc[i][j] = 0.0f;
    float m0 = -1e30f, m1 = -1e30f, l0 = 0.0f, l1 = 0.0f;

    const int mrow0 = b * GT + t0 + w * 16 + gr;
    const uint32_t* mrp0 = mbits + (size_t)mrow0 * (GF / 32);
    const uint32_t* mrp1 = mrp0 + 8 * (GF / 32);

    for (int ftile = 0; ftile < 16; ftile++) {
        if (ftile + 2 < 16)
            kv_issue(KH, KL, VH, VL, gfbase + (ftile + 2) * 64, hof,
                     sb + (SKV0 + ((ftile + 2) % 3) * KVSTG) * 2, tid);
        CP_COMMIT();

        const uint32_t stg = SKV0 + (ftile % 3) * KVSTG;

        uint2 mw0 = *(const uint2*)(mrp0 + ftile * 2);
        uint2 mw1 = *(const uint2*)(mrp1 + ftile * 2);
        uint32_t wA[2] = { mw0.x, mw0.y };
        uint32_t wB[2] = { mw1.x, mw1.y };

        // S = Q K^T (bf16x3)
        float sacc[8][4];
#pragma unroll
        for (int nt = 0; nt < 8; nt++) {
#pragma unroll
            for (int j = 0; j < 4; j++) sacc[nt][j] = 0.0f;
        }
#pragma unroll
        for (int nt = 0; nt < 8; nt++) {
            uint32_t bh[8], bl[8];
#pragma unroll
            for (int kcg = 0; kcg < 2; kcg++) {
                uint32_t ad = sb + (stg + (nt * 8 + lr) * ALD + kcg * 32 + seg * 8) * 2;
                ldsm4(&bh[kcg * 4], ad);
                ldsm4(&bl[kcg * 4], ad + KVARR * 2);
            }
#pragma unroll
            for (int kc = 0; kc < 4; kc++) {
                mma16816(sacc[nt], qh[kc], &bh[kc * 2]);
                mma16816(sacc[nt], qh[kc], &bl[kc * 2]);
                mma16816(sacc[nt], ql[kc], &bh[kc * 2]);
            }
        }

        // mask + scale + row max
        float rm0 = -1e30f, rm1 = -1e30f;
#pragma unroll
        for (int nt = 0; nt < 8; nt++) {
            uint32_t sh = (nt & 3) * 8 + qc;
            uint32_t bA = wA[nt >> 2] >> sh;
            uint32_t bB = wB[nt >> 2] >> sh;
            float s0 = (bA & 1u) ? sacc[nt][0] * 0.125f : -10000.0f;
            float s1 = (bA & 2u) ? sacc[nt][1] * 0.125f : -10000.0f;
            float s2 = (bB & 1u) ? sacc[nt][2] * 0.125f : -10000.0f;
            float s3 = (bB & 2u) ? sacc[nt][3] * 0.125f : -10000.0f;
            sacc[nt][0] = s0; sacc[nt][1] = s1; sacc[nt][2] = s2; sacc[nt][3] = s3;
            rm0 = fmaxf(rm0, fmaxf(s0, s1));
            rm1 = fmaxf(rm1, fmaxf(s2, s3));
        }
        rm0 = fmaxf(rm0, __shfl_xor_sync(0xffffffffu, rm0, 1));
        rm0 = fmaxf(rm0, __shfl_xor_sync(0xffffffffu, rm0, 2));
        rm1 = fmaxf(rm1, __shfl_xor_sync(0xffffffffu, rm1, 1));
        rm1 = fmaxf(rm1, __shfl_xor_sync(0xffffffffu, rm1, 2));
        float mn0 = fmaxf(m0, rm0), mn1 = fmaxf(m1, rm1);
        float c0 = fast_exp(m0 - mn0), c1 = fast_exp(m1 - mn1);
        m0 = mn0; m1 = mn1;

        // P = exp(s-m), pack A-frags hi/lo, row sums
        uint32_t pah[4][4], pal[4][4];
        float rs0 = 0.0f, rs1 = 0.0f;
#pragma unroll
        for (int kc = 0; kc < 4; kc++) {
            float p0 = fast_exp(sacc[2*kc][0] - m0);
            float p1 = fast_exp(sacc[2*kc][1] - m0);
            float p2 = fast_exp(sacc[2*kc][2] - m1);
            float p3 = fast_exp(sacc[2*kc][3] - m1);
            float p4 = fast_exp(sacc[2*kc+1][0] - m0);
            float p5 = fast_exp(sacc[2*kc+1][1] - m0);
            float p6 = fast_exp(sacc[2*kc+1][2] - m1);
            float p7 = fast_exp(sacc[2*kc+1][3] - m1);
            rs0 += (p0 + p1) + (p4 + p5);
            rs1 += (p2 + p3) + (p6 + p7);
            uint32_t h0 = packbf(p1, p0), h1 = packbf(p3, p2);
            uint32_t h2 = packbf(p5, p4), h3 = packbf(p7, p6);
            pah[kc][0] = h0; pah[kc][1] = h1; pah[kc][2] = h2; pah[kc][3] = h3;
            pal[kc][0] = packbf(p1 - bfhi(h0), p0 - bflo(h0));
            pal[kc][1] = packbf(p3 - bfhi(h1), p2 - bflo(h1));
            pal[kc][2] = packbf(p5 - bfhi(h2), p4 - bflo(h2));
            pal[kc][3] = packbf(p7 - bfhi(h3), p6 - bflo(h3));
        }
        rs0 += __shfl_xor_sync(0xffffffffu, rs0, 1);
        rs0 += __shfl_xor_sync(0xffffffffu, rs0, 2);
        rs1 += __shfl_xor_sync(0xffffffffu, rs1, 1);
        rs1 += __shfl_xor_sync(0xffffffffu, rs1, 2);
        l0 = l0 * c0 + rs0;
        l1 = l1 * c1 + rs1;

#pragma unroll
        for (int nt = 0; nt < 8; nt++) {
            oacc[nt][0] *= c0; oacc[nt][1] *= c0;
            oacc[nt][2] *= c1; oacc[nt][3] *= c1;
        }

        // O += P V (bf16x3)
#pragma unroll
        for (int kcg = 0; kcg < 2; kcg++) {
#pragma unroll
            for (int nt = 0; nt < 8; nt++) {
                uint32_t bvh[4], bvl[4];
                uint32_t ad = sb + (stg + 2*KVARR + (kcg * 32 + seg * 8 + lr) * ALD + nt * 8) * 2;
                ldsm4t(bvh, ad);
                ldsm4t(bvl, ad + KVARR * 2);
                mma16816(oacc[nt], pah[2*kcg],     bvh);
                mma16816(oacc[nt], pal[2*kcg],     bvh);
                mma16816(oacc[nt], pah[2*kcg],     bvl);
                mma16816(oacc[nt], pah[2*kcg+1],   &bvh[2]);
                mma16816(oacc[nt], pal[2*kcg+1],   &bvh[2]);
                mma16816(oacc[nt], pah[2*kcg+1],   &bvl[2]);
            }
        }

        CP_WAIT1();
        __syncthreads();
    }

    // Epilogue
    float inv0 = 1.0f / l0, inv1 = 1.0f / l1;
    size_t orow = (size_t)(b * GT + t0 + w * 16 + gr) * DIM + hof;
#pragma unroll
    for (int nt = 0; nt < 8; nt++) {
        int col = nt * 8 + qc;
        float v0 = oacc[nt][0] * inv0, v1 = oacc[nt][1] * inv0;
        float v2 = oacc[nt][2] * inv1, v3 = oacc[nt][3] * inv1;
        uint32_t h0 = packbf(v1, v0);
        uint32_t l0p = packbf(v1 - bfhi(h0), v0 - bflo(h0));
        uint32_t h1 = packbf(v3, v2);
        uint32_t l1p = packbf(v3 - bfhi(h1), v2 - bflo(h1));
        *(uint32_t*)&AHo[orow + col] = h0;
        *(uint32_t*)&ALo[orow + col] = l0p;
        *(uint32_t*)&AHo[orow + 8 * DIM + col] = h1;
        *(uint32_t*)&ALo[orow + 8 * DIM + col] = l1p;
    }
}

// ---------------------------------------------------------------------------
// Launch
// ---------------------------------------------------------------------------
extern "C" void kernel_launch(void* const* d_in, const int* in_sizes, int n_in,
                              void* d_out, int out_size)
{
    const float* X_to   = (const float*)d_in[0];
    const float* X_from = (const float*)d_in[1];
    const int*   maskp  = (const int*)  d_in[2];
    const float* Wq = (const float*)d_in[3];
    const float* bq = (const float*)d_in[4];
    const float* Wk = (const float*)d_in[5];
    const float* bk = (const float*)d_in[6];
    const float* Wv = (const float*)d_in[7];
    const float* bv = (const float*)d_in[8];
    const float* Wo = (const float*)d_in[9];
    const float* bo = (const float*)d_in[10];
    float* out = (float*)d_out;

    __nv_bfloat16 *QH,*QL,*KH,*KL,*VH,*VL,*AH,*AL;
    __nv_bfloat16 *XtH,*XtL,*XfH,*XfL;
    __nv_bfloat16 *WqH,*WqL,*WkH,*WkL,*WvH,*WvL,*WoH,*WoL;
    uint32_t* mbits;
    cudaGetSymbolAddress((void**)&QH, g_QH); cudaGetSymbolAddress((void**)&QL, g_QL);
    cudaGetSymbolAddress((void**)&KH, g_KH); cudaGetSymbolAddress((void**)&KL, g_KL);
    cudaGetSymbolAddress((void**)&VH, g_VH); cudaGetSymbolAddress((void**)&VL, g_VL);
    cudaGetSymbolAddress((void**)&AH, g_AH); cudaGetSymbolAddress((void**)&AL, g_AL);
    cudaGetSymbolAddress((void**)&XtH, g_XtH); cudaGetSymbolAddress((void**)&XtL, g_XtL);
    cudaGetSymbolAddress((void**)&XfH, g_XfH); cudaGetSymbolAddress((void**)&XfL, g_XfL);
    cudaGetSymbolAddress((void**)&WqH, g_WqH); cudaGetSymbolAddress((void**)&WqL, g_WqL);
    cudaGetSymbolAddress((void**)&WkH, g_WkH); cudaGetSymbolAddress((void**)&WkL, g_WkL);
    cudaGetSymbolAddress((void**)&WvH, g_WvH); cudaGetSymbolAddress((void**)&WvL, g_WvL);
    cudaGetSymbolAddress((void**)&WoH, g_WoH); cudaGetSymbolAddress((void**)&WoL, g_WoL);
    cudaGetSymbolAddress((void**)&mbits, g_mbits);

    cudaFuncSetAttribute(gemm_mma_bf16x3,
                         cudaFuncAttributeMaxDynamicSharedMemorySize, GEMM_SMEM);
    cudaFuncSetAttribute(attn_mma,
                         cudaFuncAttributeMaxDynamicSharedMemorySize, ATT_SMEM);

    prep_split<<<NPREP / 256, 256>>>((const float4*)X_to, (const float4*)X_from,
                                     (const float4*)Wq, (const float4*)Wk,
                                     (const float4*)Wv, (const float4*)Wo);
    pack_mask<<<(MTOT * GF) / 256, 256>>>(maskp, mbits);

    dim3 gg(DIM / BN, MTOT / BM);   // (8, 32)

    // Projections -> bf16 hi/lo pairs. NOTE reference's swap: K<=Wv/bv, V<=Wk/bk.
    gemm_mma_bf16x3<<<gg, 256, GEMM_SMEM>>>(XtH, XtL, WqH, WqL, bq, nullptr, QH, QL);
    gemm_mma_bf16x3<<<gg, 256, GEMM_SMEM>>>(XfH, XfL, WvH, WvL, bv, nullptr, KH, KL);
    gemm_mma_bf16x3<<<gg, 256, GEMM_SMEM>>>(XfH, XfL, WkH, WkL, bk, nullptr, VH, VL);

    dim3 ag(GT / 128, GH, GB);      // (8, 16, 4)
    attn_mma<<<ag, 256, ATT_SMEM>>>(QH, QL, KH, KL, VH, VL, mbits, AH, AL);

    // Output projection (fp32 out)
    gemm_mma_bf16x3<<<gg, 256, GEMM_SMEM>>>(AH, AL, WoH, WoL, bo, out, nullptr, nullptr);
}